// round 5
// baseline (speedup 1.0000x reference)
#include <cuda_runtime.h>
#include <math.h>
#include <stdint.h>

// Problem dims (fixed by the dataset)
constexpr int BATCH = 16384;
constexpr int D_IN  = 2048;
constexpr int H1D   = 1024;
constexpr int H2D   = 512;
constexpr int DLAT  = 256;
constexpr int KCODE = 1024;

// ---------------------------------------------------------------------------
// Scratch (allocation-free contract: __device__ globals)
// ---------------------------------------------------------------------------
__device__ float g_h1[(size_t)BATCH * H1D];     // enc h1 / VQ scores / dec h1
__device__ float g_h2[(size_t)BATCH * H2D];     // enc h2 / dec h2
__device__ float g_res[(size_t)BATCH * DLAT];   // z after LN, then running residual
__device__ float g_zq[(size_t)BATCH * DLAT];    // z_q_total
__device__ float g_vloss[BATCH];
__device__ int   g_idx[BATCH * 3];
__device__ float g_cbn[3 * KCODE];
// transposed weights, [N,K] row-major (K-major rows for the B operand)
__device__ float g_w1t[(size_t)H1D * D_IN];
__device__ float g_w2t[(size_t)H2D * H1D];
__device__ float g_w3t[(size_t)DLAT * H2D];
__device__ float g_d1t[(size_t)H2D * DLAT];
__device__ float g_d2t[(size_t)H1D * H2D];
__device__ float g_d3t[(size_t)D_IN * H1D];

// ---------------------------------------------------------------------------
// Helpers
// ---------------------------------------------------------------------------
__device__ __forceinline__ float tf32_rna(float a) {
    uint32_t r;
    asm("cvt.rna.tf32.f32 %0, %1;" : "=r"(r) : "f"(a));
    return __uint_as_float(r);
}

// m16n8k8 tf32 MMA (row.col), fp32 accumulate
__device__ __forceinline__ void mma8(float d[4], const float a[4], const float b[2]) {
    asm volatile(
        "mma.sync.aligned.m16n8k8.row.col.f32.tf32.tf32.f32 "
        "{%0,%1,%2,%3}, {%4,%5,%6,%7}, {%8,%9}, {%0,%1,%2,%3};\n"
        : "+f"(d[0]), "+f"(d[1]), "+f"(d[2]), "+f"(d[3])
        : "r"(__float_as_uint(a[0])), "r"(__float_as_uint(a[1])),
          "r"(__float_as_uint(a[2])), "r"(__float_as_uint(a[3])),
          "r"(__float_as_uint(b[0])), "r"(__float_as_uint(b[1])));
}

// Pair-packed tile layout: [128 rows][16 floats], 64B row stride.
// Element (row, k) at float pos = ((k>>3)*4 + (k&3))*2 + ((k>>2)&1),
// then byte offset XOR ((row>>1)&1)*48.  Pairs (k, k+4) are float2-adjacent.
__device__ __forceinline__ uint32_t tile_sw(uint32_t row) {
    return ((row >> 1) & 1u) * 48u;
}

// A fragment (16x8) for m16n8k8, via 2x LDS.64:
//   d0 = (row,   k), (row,   k+4);  d1 = (row+8, k), (row+8, k+4)
__device__ __forceinline__ void ld_afrag(const char* base, int mt, int ks,
                                         int lane, float f[4]) {
    uint32_t row = mt * 16 + (lane >> 2);
    uint32_t c   = (uint32_t)(ks * 32 + (lane & 3) * 8) ^ tile_sw(row);
    float2 d0 = *(const float2*)(base + row * 64 + c);
    float2 d1 = *(const float2*)(base + (row + 8) * 64 + c);  // same swizzle (row+8)
    f[0] = d0.x; f[1] = d1.x; f[2] = d0.y; f[3] = d1.y;
}

// B fragment (8x8, B^T stored [n][k]) via 1x LDS.64: (n,k),(n,k+4)
__device__ __forceinline__ void ld_bfrag(const char* base, int nt, int ks,
                                         int lane, float f[2]) {
    uint32_t row = nt * 8 + (lane >> 2);
    uint32_t c   = (uint32_t)(ks * 32 + (lane & 3) * 8) ^ tile_sw(row);
    float2 d = *(const float2*)(base + row * 64 + c);
    f[0] = d.x; f[1] = d.y;
}

// ---------------------------------------------------------------------------
// tf32 mma.sync GEMM: C[M,N] = act(A[M,K] @ B^T + bias)
//   NTERMS==3: split tf32 (hi*hi + hi*lo + lo*hi) ~ fp32 accuracy
//   NTERMS==1: single-pass tf32
// Tile 128x128, BK=16, 256 threads, 8 warps (2 m x 4 n), 64x32 per warp.
// Stage (NT3): A_hi 8K, B_hi 8K, A_lo 8K, B_lo 8K -> 32KB. 2 stages; 2 CTAs/SM.
// ---------------------------------------------------------------------------
template <int NTERMS, bool RELU, bool HASBIAS>
__global__ __launch_bounds__(256, 2)
void mma_gemm(const float* __restrict__ A, const float* __restrict__ B,
              const float* __restrict__ bias, float* __restrict__ C,
              int N, int Kd)
{
    extern __shared__ char smem[];
    constexpr int TILEB = 8192;
    constexpr int STAGE = (NTERMS == 3) ? 32768 : 16384;

    const int tid  = threadIdx.x;
    const int wid  = tid >> 5;
    const int lane = tid & 31;
    const int wm   = wid & 1;       // 0..1 -> 64 rows
    const int wn   = wid >> 1;      // 0..3 -> 32 cols

    const int nk = Kd >> 4;         // BK=16 chunks
    const float* Ag = A + (size_t)(blockIdx.y * 128) * Kd;
    const float* Bg = B + (size_t)(blockIdx.x * 128) * Kd;

    // staging role: thread -> (row r, ks group hf of the 16-wide k chunk)
    const int r  = tid >> 1;
    const int hf = tid & 1;
    const uint32_t rowoff = (uint32_t)r * 64;
    const uint32_t sw     = tile_sw((uint32_t)r);
    const uint32_t so0    = rowoff + (((uint32_t)hf * 32 + 0u)  ^ sw);
    const uint32_t so1    = rowoff + (((uint32_t)hf * 32 + 16u) ^ sw);

    float acc[4][4][4];
#pragma unroll
    for (int i = 0; i < 4; i++)
#pragma unroll
        for (int j = 0; j < 4; j++)
#pragma unroll
            for (int q = 0; q < 4; q++) acc[i][j][q] = 0.0f;

    float4 va[2], vb[2];

    auto ldg = [&](int k0) {
        const float4* pa = (const float4*)(Ag + (size_t)r * Kd + k0 * 16 + hf * 8);
        const float4* pb = (const float4*)(Bg + (size_t)r * Kd + k0 * 16 + hf * 8);
        va[0] = pa[0]; va[1] = pa[1];
        vb[0] = pb[0]; vb[1] = pb[1];
    };

    // pack pairs (k, k+4) adjacent: {v0.x,v1.x,v0.y,v1.y}, {v0.z,v1.z,v0.w,v1.w}
    auto stage_store = [&](int s) {
        char* st = smem + s * STAGE;
        float4 ha0, ha1, hb0, hb1;
        ha0.x = tf32_rna(va[0].x); ha0.y = tf32_rna(va[1].x);
        ha0.z = tf32_rna(va[0].y); ha0.w = tf32_rna(va[1].y);
        ha1.x = tf32_rna(va[0].z); ha1.y = tf32_rna(va[1].z);
        ha1.z = tf32_rna(va[0].w); ha1.w = tf32_rna(va[1].w);
        hb0.x = tf32_rna(vb[0].x); hb0.y = tf32_rna(vb[1].x);
        hb0.z = tf32_rna(vb[0].y); hb0.w = tf32_rna(vb[1].y);
        hb1.x = tf32_rna(vb[0].z); hb1.y = tf32_rna(vb[1].z);
        hb1.z = tf32_rna(vb[0].w); hb1.w = tf32_rna(vb[1].w);
        *(float4*)(st + so0)         = ha0;
        *(float4*)(st + so1)         = ha1;
        *(float4*)(st + TILEB + so0) = hb0;
        *(float4*)(st + TILEB + so1) = hb1;
        if (NTERMS == 3) {
            float4 la0, la1, lb0, lb1;
            la0.x = tf32_rna(va[0].x - ha0.x); la0.y = tf32_rna(va[1].x - ha0.y);
            la0.z = tf32_rna(va[0].y - ha0.z); la0.w = tf32_rna(va[1].y - ha0.w);
            la1.x = tf32_rna(va[0].z - ha1.x); la1.y = tf32_rna(va[1].z - ha1.y);
            la1.z = tf32_rna(va[0].w - ha1.z); la1.w = tf32_rna(va[1].w - ha1.w);
            lb0.x = tf32_rna(vb[0].x - hb0.x); lb0.y = tf32_rna(vb[1].x - hb0.y);
            lb0.z = tf32_rna(vb[0].y - hb0.z); lb0.w = tf32_rna(vb[1].y - hb0.w);
            lb1.x = tf32_rna(vb[0].z - hb1.x); lb1.y = tf32_rna(vb[1].z - hb1.y);
            lb1.z = tf32_rna(vb[0].w - hb1.z); lb1.w = tf32_rna(vb[1].w - hb1.w);
            *(float4*)(st + 2 * TILEB + so0) = la0;
            *(float4*)(st + 2 * TILEB + so1) = la1;
            *(float4*)(st + 3 * TILEB + so0) = lb0;
            *(float4*)(st + 3 * TILEB + so1) = lb1;
        }
    };

    ldg(0);
    stage_store(0);
    __syncthreads();

    for (int k0 = 0; k0 < nk; k0++) {
        if (k0 + 1 < nk) ldg(k0 + 1);

        const char* st = smem + (k0 & 1) * STAGE;
#pragma unroll
        for (int ks = 0; ks < 2; ks++) {
            float bh[4][2], bl[4][2];
#pragma unroll
            for (int nt = 0; nt < 4; nt++) {
                ld_bfrag(st + TILEB, wn * 4 + nt, ks, lane, bh[nt]);
                if (NTERMS == 3)
                    ld_bfrag(st + 3 * TILEB, wn * 4 + nt, ks, lane, bl[nt]);
            }
#pragma unroll
            for (int mt = 0; mt < 4; mt++) {
                float ah[4], al[4];
                ld_afrag(st, wm * 4 + mt, ks, lane, ah);
                if (NTERMS == 3)
                    ld_afrag(st + 2 * TILEB, wm * 4 + mt, ks, lane, al);
#pragma unroll
                for (int nt = 0; nt < 4; nt++) {
                    mma8(acc[mt][nt], ah, bh[nt]);
                    if (NTERMS == 3) {
                        mma8(acc[mt][nt], ah, bl[nt]);
                        mma8(acc[mt][nt], al, bh[nt]);
                    }
                }
            }
        }

        if (k0 + 1 < nk) stage_store((k0 + 1) & 1);
        __syncthreads();
    }

    // ---- epilogue ----
    const int row0 = blockIdx.y * 128 + wm * 64 + (lane >> 2);
    const int col0 = blockIdx.x * 128 + wn * 32 + (lane & 3) * 2;
#pragma unroll
    for (int mt = 0; mt < 4; mt++) {
#pragma unroll
        for (int nt = 0; nt < 4; nt++) {
            int rr = row0 + mt * 16;
            int cc = col0 + nt * 8;
            float b0 = 0.f, b1 = 0.f;
            if (HASBIAS) { b0 = __ldg(bias + cc); b1 = __ldg(bias + cc + 1); }
            float2 v0, v1;
            v0.x = acc[mt][nt][0] + b0; v0.y = acc[mt][nt][1] + b1;
            v1.x = acc[mt][nt][2] + b0; v1.y = acc[mt][nt][3] + b1;
            if (RELU) {
                v0.x = fmaxf(v0.x, 0.f); v0.y = fmaxf(v0.y, 0.f);
                v1.x = fmaxf(v1.x, 0.f); v1.y = fmaxf(v1.y, 0.f);
            }
            *(float2*)(C + (size_t)rr * N + cc)       = v0;
            *(float2*)(C + (size_t)(rr + 8) * N + cc) = v1;
        }
    }
}

// ---------------------------------------------------------------------------
// Tiled transpose: W[K,N] -> T[N,K]
// ---------------------------------------------------------------------------
__global__ __launch_bounds__(256)
void transpose_kernel(const float* __restrict__ W, float* __restrict__ T,
                      int K, int N)
{
    __shared__ float tile[32][33];
    int n0 = blockIdx.x * 32;
    int k0 = blockIdx.y * 32;
#pragma unroll
    for (int i = 0; i < 32; i += 8)
        tile[threadIdx.y + i][threadIdx.x] =
            W[(size_t)(k0 + threadIdx.y + i) * N + n0 + threadIdx.x];
    __syncthreads();
#pragma unroll
    for (int i = 0; i < 32; i += 8)
        T[(size_t)(n0 + threadIdx.y + i) * K + k0 + threadIdx.x] =
            tile[threadIdx.x][threadIdx.y + i];
}

// ---------------------------------------------------------------------------
// LayerNorm over DLAT=256, warp per row
// ---------------------------------------------------------------------------
__global__ __launch_bounds__(256)
void ln_kernel(float* __restrict__ z, const float* __restrict__ g,
               const float* __restrict__ b)
{
    int row  = blockIdx.x * 8 + (threadIdx.x >> 5);
    int lane = threadIdx.x & 31;
    float* zr = z + (size_t)row * DLAT;

    float v[8];
    float s = 0.f;
#pragma unroll
    for (int i = 0; i < 8; i++) { v[i] = zr[lane + 32 * i]; s += v[i]; }
#pragma unroll
    for (int o = 16; o; o >>= 1) s += __shfl_xor_sync(0xffffffffu, s, o);
    float mu = s * (1.0f / 256.0f);

    float s2 = 0.f;
#pragma unroll
    for (int i = 0; i < 8; i++) { float d = v[i] - mu; s2 += d * d; }
#pragma unroll
    for (int o = 16; o; o >>= 1) s2 += __shfl_xor_sync(0xffffffffu, s2, o);
    float var = s2 * (1.0f / 256.0f);
    float rs  = 1.0f / sqrtf(var + 1e-5f);

#pragma unroll
    for (int i = 0; i < 8; i++) {
        int col = lane + 32 * i;
        zr[col] = (v[i] - mu) * rs * g[col] + b[col];
    }
}

// ---------------------------------------------------------------------------
// Codebook row norms: warp per code
// ---------------------------------------------------------------------------
__global__ __launch_bounds__(256)
void cbnorm_kernel(const float* __restrict__ cb0, const float* __restrict__ cb1,
                   const float* __restrict__ cb2, float* __restrict__ cbn)
{
    int code = blockIdx.x * 8 + (threadIdx.x >> 5);
    int lane = threadIdx.x & 31;
    const float* cb = (code < KCODE) ? cb0 : (code < 2 * KCODE ? cb1 : cb2);
    const float* c  = cb + (size_t)(code & (KCODE - 1)) * DLAT;
    float s = 0.f;
#pragma unroll
    for (int i = 0; i < 8; i++) { float v = c[lane + 32 * i]; s += v * v; }
#pragma unroll
    for (int o = 16; o; o >>= 1) s += __shfl_xor_sync(0xffffffffu, s, o);
    if (lane == 0) cbn[code] = s;
}

// ---------------------------------------------------------------------------
// Fused VQ step: argmin over K=1024 (first-occurrence ties, JAX numerics)
// then straight-through update of res/zq/vloss and idx write. Warp per row.
// ---------------------------------------------------------------------------
__global__ __launch_bounds__(256)
void vq_step(float* __restrict__ res, const float* __restrict__ scores,
             const float* __restrict__ cbn, const float* __restrict__ cb,
             float* __restrict__ zq, float* __restrict__ vloss,
             int* __restrict__ idx_out, int stage)
{
    int row  = blockIdx.x * 8 + (threadIdx.x >> 5);
    int lane = threadIdx.x & 31;

    float* r = res + (size_t)row * DLAT;
    float rv[8];
    float s = 0.f;
#pragma unroll
    for (int i = 0; i < 8; i++) { rv[i] = r[lane + 32 * i]; s += rv[i] * rv[i]; }
#pragma unroll
    for (int o = 16; o; o >>= 1) s += __shfl_xor_sync(0xffffffffu, s, o);
    float rnorm = s;

    const float* sr = scores + (size_t)row * KCODE;
    float best = INFINITY;
    int bi = 0;
#pragma unroll 4
    for (int n = lane; n < KCODE; n += 32) {
        float d = (rnorm - 2.0f * sr[n]) + cbn[n];
        if (d < best) { best = d; bi = n; }
    }
#pragma unroll
    for (int o = 16; o; o >>= 1) {
        float ov = __shfl_xor_sync(0xffffffffu, best, o);
        int   oi = __shfl_xor_sync(0xffffffffu, bi, o);
        if (ov < best || (ov == best && oi < bi)) { best = ov; bi = oi; }
    }
    bi = __shfl_sync(0xffffffffu, bi, 0);
    if (lane == 0) idx_out[row * 3 + stage] = bi;

    // straight-through update (replicates JAX numerics exactly)
    const float* c = cb + (size_t)bi * DLAT;
    float* q = zq + (size_t)row * DLAT;
    float se = 0.f;
#pragma unroll
    for (int i = 0; i < 8; i++) {
        int col = lane + 32 * i;
        float ev = c[col];
        float diff = rv[i] - ev;
        se += diff * diff;
        float t   = ev - rv[i];      // sg(e - r)
        float zqe = rv[i] + t;       // straight-through z_q
        r[col] = rv[i] - zqe;        // residual - sg(z_q)
        q[col] = (stage == 0) ? zqe : (q[col] + zqe);
    }
#pragma unroll
    for (int o = 16; o; o >>= 1) se += __shfl_xor_sync(0xffffffffu, se, o);
    if (lane == 0) {
        float m = se * (1.0f / 256.0f);
        float l = m + 0.25f * m;
        vloss[row] = (stage == 0) ? l : (vloss[row] + l);
    }
}

// ---------------------------------------------------------------------------
// Finalize: recon loss, total loss, idx -> float
// ---------------------------------------------------------------------------
__global__ __launch_bounds__(256)
void finalize_kernel(const float* __restrict__ x, const float* __restrict__ xhat,
                     const float* __restrict__ vloss, const int* __restrict__ idx,
                     float* __restrict__ out_loss, float* __restrict__ out_idx)
{
    int row  = blockIdx.x * 8 + (threadIdx.x >> 5);
    int lane = threadIdx.x & 31;

    const float* xr = x    + (size_t)row * D_IN;
    const float* hr = xhat + (size_t)row * D_IN;
    float s = 0.f;
#pragma unroll 8
    for (int i = 0; i < 64; i++) {
        int col = lane + 32 * i;
        float d = hr[col] - xr[col];
        s += d * d;
    }
#pragma unroll
    for (int o = 16; o; o >>= 1) s += __shfl_xor_sync(0xffffffffu, s, o);
    if (lane == 0) {
        float recon = s * (1.0f / 2048.0f);
        out_loss[row] = vloss[row] + recon;
    }
    if (lane < 3) out_idx[row * 3 + lane] = (float)idx[row * 3 + lane];
}

// ---------------------------------------------------------------------------
// Launch
// ---------------------------------------------------------------------------
extern "C" void kernel_launch(void* const* d_in, const int* in_sizes, int n_in,
                              void* d_out, int out_size)
{
    const float* x      = (const float*)d_in[0];
    const float* encW1  = (const float*)d_in[1];
    const float* encb1  = (const float*)d_in[2];
    const float* encW2  = (const float*)d_in[3];
    const float* encb2  = (const float*)d_in[4];
    const float* encW3  = (const float*)d_in[5];
    const float* encb3  = (const float*)d_in[6];
    const float* ln_g   = (const float*)d_in[7];
    const float* ln_b   = (const float*)d_in[8];
    const float* cb0    = (const float*)d_in[9];
    const float* cb1    = (const float*)d_in[10];
    const float* cb2    = (const float*)d_in[11];
    const float* decW1  = (const float*)d_in[12];
    const float* decb1  = (const float*)d_in[13];
    const float* decW2  = (const float*)d_in[14];
    const float* decb2  = (const float*)d_in[15];
    const float* decW3  = (const float*)d_in[16];
    const float* decb3  = (const float*)d_in[17];

    float *h1, *h2, *res, *zq, *vloss, *cbn;
    float *w1t, *w2t, *w3t, *d1t, *d2t, *d3t;
    int* idx;
    cudaGetSymbolAddress((void**)&h1, g_h1);
    cudaGetSymbolAddress((void**)&h2, g_h2);
    cudaGetSymbolAddress((void**)&res, g_res);
    cudaGetSymbolAddress((void**)&zq, g_zq);
    cudaGetSymbolAddress((void**)&vloss, g_vloss);
    cudaGetSymbolAddress((void**)&cbn, g_cbn);
    cudaGetSymbolAddress((void**)&idx, g_idx);
    cudaGetSymbolAddress((void**)&w1t, g_w1t);
    cudaGetSymbolAddress((void**)&w2t, g_w2t);
    cudaGetSymbolAddress((void**)&w3t, g_w3t);
    cudaGetSymbolAddress((void**)&d1t, g_d1t);
    cudaGetSymbolAddress((void**)&d2t, g_d2t);
    cudaGetSymbolAddress((void**)&d3t, g_d3t);

    float* xhat     = (float*)d_out;
    float* out_loss = xhat + (size_t)BATCH * D_IN;
    float* out_idx  = out_loss + BATCH;

    const int SMEM3 = 2 * 32768;   // 64 KB -> 2 CTAs/SM
    const int SMEM1 = 2 * 16384;   // 32 KB
    cudaFuncSetAttribute((const void*)mma_gemm<3, true,  true >, cudaFuncAttributeMaxDynamicSharedMemorySize, SMEM3);
    cudaFuncSetAttribute((const void*)mma_gemm<3, false, true >, cudaFuncAttributeMaxDynamicSharedMemorySize, SMEM3);
    cudaFuncSetAttribute((const void*)mma_gemm<3, false, false>, cudaFuncAttributeMaxDynamicSharedMemorySize, SMEM3);
    cudaFuncSetAttribute((const void*)mma_gemm<1, true,  true >, cudaFuncAttributeMaxDynamicSharedMemorySize, SMEM1);
    cudaFuncSetAttribute((const void*)mma_gemm<1, false, true >, cudaFuncAttributeMaxDynamicSharedMemorySize, SMEM1);

    const dim3 blk(256);
    const dim3 tblk(32, 8);
    const int MB = BATCH / 128;          // 128
    const int warpGrid = BATCH / 8;      // 2048

    // ---- prep: transpose weights to [N,K]; codebook norms ----
    transpose_kernel<<<dim3(H1D / 32, D_IN / 32), tblk>>>(encW1, w1t, D_IN, H1D);
    transpose_kernel<<<dim3(H2D / 32, H1D / 32), tblk>>>(encW2, w2t, H1D, H2D);
    transpose_kernel<<<dim3(DLAT / 32, H2D / 32), tblk>>>(encW3, w3t, H2D, DLAT);
    transpose_kernel<<<dim3(H2D / 32, DLAT / 32), tblk>>>(decW1, d1t, DLAT, H2D);
    transpose_kernel<<<dim3(H1D / 32, H2D / 32), tblk>>>(decW2, d2t, H2D, H1D);
    transpose_kernel<<<dim3(D_IN / 32, H1D / 32), tblk>>>(decW3, d3t, H1D, D_IN);
    cbnorm_kernel<<<3 * KCODE / 8, blk>>>(cb0, cb1, cb2, cbn);

    // ---- encoder (tf32x3 split = fp32 accuracy) ----
    mma_gemm<3, true,  true ><<<dim3(H1D / 128, MB), blk, SMEM3>>>(x,  w1t, encb1, h1,  H1D,  D_IN);
    mma_gemm<3, true,  true ><<<dim3(H2D / 128, MB), blk, SMEM3>>>(h1, w2t, encb2, h2,  H2D,  H1D);
    mma_gemm<3, false, true ><<<dim3(DLAT / 128, MB), blk, SMEM3>>>(h2, w3t, encb3, res, DLAT, H2D);

    ln_kernel<<<warpGrid, blk>>>(res, ln_g, ln_b);

    // ---- residual VQ (scores in h1 scratch; fused argmin+update) ----
    for (int s = 0; s < 3; s++) {
        const float* cb = (s == 0) ? cb0 : (s == 1 ? cb1 : cb2);
        mma_gemm<3, false, false><<<dim3(KCODE / 128, MB), blk, SMEM3>>>(res, cb, nullptr, h1, KCODE, DLAT);
        vq_step<<<warpGrid, blk>>>(res, h1, cbn + s * KCODE, cb, zq, vloss, idx, s);
    }

    // ---- decoder (single-pass tf32; post-argmin, tolerance-safe) ----
    mma_gemm<1, true,  true ><<<dim3(H2D / 128, MB), blk, SMEM1>>>(zq, d1t, decb1, h2,   H2D,  DLAT);
    mma_gemm<1, true,  true ><<<dim3(H1D / 128, MB), blk, SMEM1>>>(h2, d2t, decb2, h1,   H1D,  H2D);
    mma_gemm<1, false, true ><<<dim3(D_IN / 128, MB), blk, SMEM1>>>(h1, d3t, decb3, xhat, D_IN, H1D);

    finalize_kernel<<<warpGrid, blk>>>(x, xhat, vloss, idx, out_loss, out_idx);
}

// round 6
// speedup vs baseline: 1.0885x; 1.0885x over previous
#include <cuda_runtime.h>
#include <math.h>
#include <stdint.h>

// Problem dims (fixed by the dataset)
constexpr int BATCH = 16384;
constexpr int D_IN  = 2048;
constexpr int H1D   = 1024;
constexpr int H2D   = 512;
constexpr int DLAT  = 256;
constexpr int KCODE = 1024;

// ---------------------------------------------------------------------------
// Scratch (allocation-free contract: __device__ globals)
// ---------------------------------------------------------------------------
__device__ float g_h1[(size_t)BATCH * H1D];     // enc h1 / VQ scores / dec h1
__device__ float g_h2[(size_t)BATCH * H2D];     // enc h2 / dec h2
__device__ float g_res[(size_t)BATCH * DLAT];   // z after LN, then running residual
__device__ float g_zq[(size_t)BATCH * DLAT];    // z_q_total
__device__ float g_vloss[BATCH];
__device__ int   g_idx[BATCH * 3];
__device__ float g_cbn[3 * KCODE];
// transposed weights, [N,K] row-major (K-major rows for the B operand)
__device__ float g_w1t[(size_t)H1D * D_IN];
__device__ float g_w2t[(size_t)H2D * H1D];
__device__ float g_w3t[(size_t)DLAT * H2D];
__device__ float g_d1t[(size_t)H2D * DLAT];
__device__ float g_d2t[(size_t)H1D * H2D];
__device__ float g_d3t[(size_t)D_IN * H1D];

// ---------------------------------------------------------------------------
// Helpers
// ---------------------------------------------------------------------------
__device__ __forceinline__ float tf32_rna(float a) {
    uint32_t r;
    asm("cvt.rna.tf32.f32 %0, %1;" : "=r"(r) : "f"(a));
    return __uint_as_float(r);
}

__device__ __forceinline__ float4 cvt4(float4 v) {
    float4 h;
    h.x = tf32_rna(v.x); h.y = tf32_rna(v.y);
    h.z = tf32_rna(v.z); h.w = tf32_rna(v.w);
    return h;
}

__device__ __forceinline__ float4 sub_cvt4(float4 v, float4 h) {
    float4 l;
    l.x = tf32_rna(v.x - h.x); l.y = tf32_rna(v.y - h.y);
    l.z = tf32_rna(v.z - h.z); l.w = tf32_rna(v.w - h.w);
    return l;
}

// m16n8k8 tf32 MMA (row.col), fp32 accumulate
__device__ __forceinline__ void mma8(float d[4], const float a[4], const float b[2]) {
    asm volatile(
        "mma.sync.aligned.m16n8k8.row.col.f32.tf32.tf32.f32 "
        "{%0,%1,%2,%3}, {%4,%5,%6,%7}, {%8,%9}, {%0,%1,%2,%3};\n"
        : "+f"(d[0]), "+f"(d[1]), "+f"(d[2]), "+f"(d[3])
        : "r"(__float_as_uint(a[0])), "r"(__float_as_uint(a[1])),
          "r"(__float_as_uint(a[2])), "r"(__float_as_uint(a[3])),
          "r"(__float_as_uint(b[0])), "r"(__float_as_uint(b[1])));
}

// Tiles are [128 rows][16 floats] = 64B rows, swizzle: byte col XOR (((row>>1)&3)<<4).
// A fragment (16x8): a0:(row,k) a1:(row+8,k) a2:(row,k+4) a3:(row+8,k+4)
__device__ __forceinline__ void ld_afrag(const char* base, int mt, int ks,
                                         int lane, float f[4]) {
    uint32_t row = mt * 16 + (lane >> 2);
    uint32_t c0  = (ks * 8 + (lane & 3)) * 4;
    uint32_t s   = ((row >> 1) & 3u) << 4;   // same for row and row+8
    const char* pr0 = base + row * 64;
    const char* pr1 = pr0 + 8 * 64;
    f[0] = *(const float*)(pr0 + (c0 ^ s));
    f[1] = *(const float*)(pr1 + (c0 ^ s));
    f[2] = *(const float*)(pr0 + ((c0 + 16) ^ s));
    f[3] = *(const float*)(pr1 + ((c0 + 16) ^ s));
}

// B fragment (8x8, B^T stored [n][k]): b0:(k=lane&3, n=lane>>2) b1:(k+4, n)
__device__ __forceinline__ void ld_bfrag(const char* base, int nt, int ks,
                                         int lane, float f[2]) {
    uint32_t row = nt * 8 + (lane >> 2);     // n
    uint32_t c0  = (ks * 8 + (lane & 3)) * 4;
    uint32_t s   = ((row >> 1) & 3u) << 4;
    const char* pr = base + row * 64;
    f[0] = *(const float*)(pr + (c0 ^ s));
    f[1] = *(const float*)(pr + ((c0 + 16) ^ s));
}

// ---------------------------------------------------------------------------
// tf32 mma.sync GEMM: C[M,N] = act(A[M,K] @ B^T + bias)   (R4-proven layout)
//   NTERMS==3: split tf32 (hi*hi + hi*lo + lo*hi) ~ fp32 accuracy
//   NTERMS==1: single-pass tf32
// Tile 128x128, BK=16, 256 threads, 8 warps (2 m x 4 n), 64x32 per warp.
// ---------------------------------------------------------------------------
template <int NTERMS, bool RELU, bool HASBIAS>
__global__ __launch_bounds__(256, 2)
void mma_gemm(const float* __restrict__ A, const float* __restrict__ B,
              const float* __restrict__ bias, float* __restrict__ C,
              int N, int Kd)
{
    extern __shared__ char smem[];
    constexpr int TILEB = 8192;
    constexpr int STAGE = (NTERMS == 3) ? 32768 : 16384;

    const int tid  = threadIdx.x;
    const int wid  = tid >> 5;
    const int lane = tid & 31;
    const int wm   = wid & 1;       // 0..1 -> 64 rows
    const int wn   = wid >> 1;      // 0..3 -> 32 cols

    const int nk = Kd >> 4;         // BK=16 chunks
    const float* Ag = A + (size_t)(blockIdx.y * 128) * Kd;
    const float* Bg = B + (size_t)(blockIdx.x * 128) * Kd;

    const int r  = tid >> 1;
    const int hf = tid & 1;
    const uint32_t rowoff = (uint32_t)r * 64;
    const uint32_t sw     = ((uint32_t)(r >> 1) & 3u) << 4;

    float acc[4][4][4];
#pragma unroll
    for (int i = 0; i < 4; i++)
#pragma unroll
        for (int j = 0; j < 4; j++)
#pragma unroll
            for (int q = 0; q < 4; q++) acc[i][j][q] = 0.0f;

    float4 va[2], vb[2];

    auto ldg = [&](int k0) {
        const float4* pa = (const float4*)(Ag + (size_t)r * Kd + k0 * 16 + hf * 8);
        const float4* pb = (const float4*)(Bg + (size_t)r * Kd + k0 * 16 + hf * 8);
        va[0] = pa[0]; va[1] = pa[1];
        vb[0] = pb[0]; vb[1] = pb[1];
    };

    auto stage_store = [&](int s) {
        char* st = smem + s * STAGE;
#pragma unroll
        for (int j = 0; j < 2; j++) {
            uint32_t off = rowoff + (((uint32_t)(hf * 32 + j * 16)) ^ sw);
            float4 ha = cvt4(va[j]);
            float4 hb = cvt4(vb[j]);
            *(float4*)(st + off)         = ha;
            *(float4*)(st + TILEB + off) = hb;
            if (NTERMS == 3) {
                *(float4*)(st + 2 * TILEB + off) = sub_cvt4(va[j], ha);
                *(float4*)(st + 3 * TILEB + off) = sub_cvt4(vb[j], hb);
            }
        }
    };

    ldg(0);
    stage_store(0);
    __syncthreads();

    for (int k0 = 0; k0 < nk; k0++) {
        if (k0 + 1 < nk) ldg(k0 + 1);

        const char* st = smem + (k0 & 1) * STAGE;
#pragma unroll
        for (int ks = 0; ks < 2; ks++) {
            float bh[4][2], bl[4][2];
#pragma unroll
            for (int nt = 0; nt < 4; nt++) {
                ld_bfrag(st + TILEB, wn * 4 + nt, ks, lane, bh[nt]);
                if (NTERMS == 3)
                    ld_bfrag(st + 3 * TILEB, wn * 4 + nt, ks, lane, bl[nt]);
            }
#pragma unroll
            for (int mt = 0; mt < 4; mt++) {
                float ah[4], al[4];
                ld_afrag(st, wm * 4 + mt, ks, lane, ah);
                if (NTERMS == 3)
                    ld_afrag(st + 2 * TILEB, wm * 4 + mt, ks, lane, al);
#pragma unroll
                for (int nt = 0; nt < 4; nt++) {
                    mma8(acc[mt][nt], ah, bh[nt]);
                    if (NTERMS == 3) {
                        mma8(acc[mt][nt], ah, bl[nt]);
                        mma8(acc[mt][nt], al, bh[nt]);
                    }
                }
            }
        }

        if (k0 + 1 < nk) stage_store((k0 + 1) & 1);
        __syncthreads();
    }

    // ---- epilogue ----
    const int row0 = blockIdx.y * 128 + wm * 64 + (lane >> 2);
    const int col0 = blockIdx.x * 128 + wn * 32 + (lane & 3) * 2;
#pragma unroll
    for (int mt = 0; mt < 4; mt++) {
#pragma unroll
        for (int nt = 0; nt < 4; nt++) {
            int rr = row0 + mt * 16;
            int cc = col0 + nt * 8;
            float b0 = 0.f, b1 = 0.f;
            if (HASBIAS) { b0 = __ldg(bias + cc); b1 = __ldg(bias + cc + 1); }
            float2 v0, v1;
            v0.x = acc[mt][nt][0] + b0; v0.y = acc[mt][nt][1] + b1;
            v1.x = acc[mt][nt][2] + b0; v1.y = acc[mt][nt][3] + b1;
            if (RELU) {
                v0.x = fmaxf(v0.x, 0.f); v0.y = fmaxf(v0.y, 0.f);
                v1.x = fmaxf(v1.x, 0.f); v1.y = fmaxf(v1.y, 0.f);
            }
            *(float2*)(C + (size_t)rr * N + cc)       = v0;
            *(float2*)(C + (size_t)(rr + 8) * N + cc) = v1;
        }
    }
}

// ---------------------------------------------------------------------------
// Tiled transpose: W[K,N] -> T[N,K]
// ---------------------------------------------------------------------------
__global__ __launch_bounds__(256)
void transpose_kernel(const float* __restrict__ W, float* __restrict__ T,
                      int K, int N)
{
    __shared__ float tile[32][33];
    int n0 = blockIdx.x * 32;
    int k0 = blockIdx.y * 32;
#pragma unroll
    for (int i = 0; i < 32; i += 8)
        tile[threadIdx.y + i][threadIdx.x] =
            W[(size_t)(k0 + threadIdx.y + i) * N + n0 + threadIdx.x];
    __syncthreads();
#pragma unroll
    for (int i = 0; i < 32; i += 8)
        T[(size_t)(n0 + threadIdx.y + i) * K + k0 + threadIdx.x] =
            tile[threadIdx.x][threadIdx.y + i];
}

// ---------------------------------------------------------------------------
// LayerNorm over DLAT=256, warp per row
// ---------------------------------------------------------------------------
__global__ __launch_bounds__(256)
void ln_kernel(float* __restrict__ z, const float* __restrict__ g,
               const float* __restrict__ b)
{
    int row  = blockIdx.x * 8 + (threadIdx.x >> 5);
    int lane = threadIdx.x & 31;
    float* zr = z + (size_t)row * DLAT;

    float v[8];
    float s = 0.f;
#pragma unroll
    for (int i = 0; i < 8; i++) { v[i] = zr[lane + 32 * i]; s += v[i]; }
#pragma unroll
    for (int o = 16; o; o >>= 1) s += __shfl_xor_sync(0xffffffffu, s, o);
    float mu = s * (1.0f / 256.0f);

    float s2 = 0.f;
#pragma unroll
    for (int i = 0; i < 8; i++) { float d = v[i] - mu; s2 += d * d; }
#pragma unroll
    for (int o = 16; o; o >>= 1) s2 += __shfl_xor_sync(0xffffffffu, s2, o);
    float var = s2 * (1.0f / 256.0f);
    float rs  = 1.0f / sqrtf(var + 1e-5f);

#pragma unroll
    for (int i = 0; i < 8; i++) {
        int col = lane + 32 * i;
        zr[col] = (v[i] - mu) * rs * g[col] + b[col];
    }
}

// ---------------------------------------------------------------------------
// Codebook row norms: warp per code
// ---------------------------------------------------------------------------
__global__ __launch_bounds__(256)
void cbnorm_kernel(const float* __restrict__ cb0, const float* __restrict__ cb1,
                   const float* __restrict__ cb2, float* __restrict__ cbn)
{
    int code = blockIdx.x * 8 + (threadIdx.x >> 5);
    int lane = threadIdx.x & 31;
    const float* cb = (code < KCODE) ? cb0 : (code < 2 * KCODE ? cb1 : cb2);
    const float* c  = cb + (size_t)(code & (KCODE - 1)) * DLAT;
    float s = 0.f;
#pragma unroll
    for (int i = 0; i < 8; i++) { float v = c[lane + 32 * i]; s += v * v; }
#pragma unroll
    for (int o = 16; o; o >>= 1) s += __shfl_xor_sync(0xffffffffu, s, o);
    if (lane == 0) cbn[code] = s;
}

// ---------------------------------------------------------------------------
// Fused VQ step with exact refinement.
// scores were computed in single-pass tf32 (noise ~2e-4 abs on d).
// Pass 1: approx min. Pass 2: every code within MARGIN of approx min gets an
// exact fp32 distance (warp-cooperative dot with r in registers); min with
// first-index tie-break. Then straight-through update (JAX numerics).
// Warp per row.
// ---------------------------------------------------------------------------
constexpr float VQ_MARGIN = 0.05f;

__global__ __launch_bounds__(256)
void vq_step(float* __restrict__ res, const float* __restrict__ scores,
             const float* __restrict__ cbn, const float* __restrict__ cb,
             float* __restrict__ zq, float* __restrict__ vloss,
             int* __restrict__ idx_out, int stage)
{
    int row  = blockIdx.x * 8 + (threadIdx.x >> 5);
    int lane = threadIdx.x & 31;

    float* r = res + (size_t)row * DLAT;
    float rv[8];
    float s = 0.f;
#pragma unroll
    for (int i = 0; i < 8; i++) { rv[i] = r[lane + 32 * i]; s += rv[i] * rv[i]; }
#pragma unroll
    for (int o = 16; o; o >>= 1) s += __shfl_xor_sync(0xffffffffu, s, o);
    const float rnorm = s;

    // pass 1: approximate min distance (value only)
    const float* sr = scores + (size_t)row * KCODE;
    float amin = INFINITY;
    float dv[32];
#pragma unroll 4
    for (int j = 0; j < 32; j++) {
        int n = lane + 32 * j;
        float d = (rnorm - 2.0f * sr[n]) + cbn[n];
        dv[j] = d;
        amin = fminf(amin, d);
    }
#pragma unroll
    for (int o = 16; o; o >>= 1)
        amin = fminf(amin, __shfl_xor_sync(0xffffffffu, amin, o));

    // pass 2: candidate mask per lane (bit j <-> code lane + 32j)
    const float thresh = amin + VQ_MARGIN;
    uint32_t cmask = 0;
#pragma unroll
    for (int j = 0; j < 32; j++)
        if (dv[j] <= thresh) cmask |= (1u << j);

    // warp-cooperative exact refinement, one candidate per iteration
    float bestv = INFINITY;
    int   bestn = KCODE;
    for (;;) {
        uint32_t ball = __ballot_sync(0xffffffffu, cmask != 0);
        if (!ball) break;
        int src = __ffs(ball) - 1;
        uint32_t m = __shfl_sync(0xffffffffu, cmask, src);
        int j = __ffs(m) - 1;
        if (lane == src) cmask &= cmask - 1;   // clear lowest bit
        int n = src + 32 * j;

        const float* c = cb + (size_t)n * DLAT;
        float dot = 0.f;
#pragma unroll
        for (int i = 0; i < 8; i++) dot += rv[i] * c[lane + 32 * i];
#pragma unroll
        for (int o = 16; o; o >>= 1) dot += __shfl_xor_sync(0xffffffffu, dot, o);

        float d = (rnorm - 2.0f * dot) + cbn[n];
        if (d < bestv || (d == bestv && n < bestn)) { bestv = d; bestn = n; }
    }
    const int bi = bestn;
    if (lane == 0) idx_out[row * 3 + stage] = bi;

    // straight-through update (replicates JAX numerics exactly)
    const float* c = cb + (size_t)bi * DLAT;
    float* q = zq + (size_t)row * DLAT;
    float se = 0.f;
#pragma unroll
    for (int i = 0; i < 8; i++) {
        int col = lane + 32 * i;
        float ev = c[col];
        float diff = rv[i] - ev;
        se += diff * diff;
        float t   = ev - rv[i];      // sg(e - r)
        float zqe = rv[i] + t;       // straight-through z_q
        r[col] = rv[i] - zqe;        // residual - sg(z_q)
        q[col] = (stage == 0) ? zqe : (q[col] + zqe);
    }
#pragma unroll
    for (int o = 16; o; o >>= 1) se += __shfl_xor_sync(0xffffffffu, se, o);
    if (lane == 0) {
        float m = se * (1.0f / 256.0f);
        float l = m + 0.25f * m;
        vloss[row] = (stage == 0) ? l : (vloss[row] + l);
    }
}

// ---------------------------------------------------------------------------
// Finalize: recon loss, total loss, idx -> float
// ---------------------------------------------------------------------------
__global__ __launch_bounds__(256)
void finalize_kernel(const float* __restrict__ x, const float* __restrict__ xhat,
                     const float* __restrict__ vloss, const int* __restrict__ idx,
                     float* __restrict__ out_loss, float* __restrict__ out_idx)
{
    int row  = blockIdx.x * 8 + (threadIdx.x >> 5);
    int lane = threadIdx.x & 31;

    const float* xr = x    + (size_t)row * D_IN;
    const float* hr = xhat + (size_t)row * D_IN;
    float s = 0.f;
#pragma unroll 8
    for (int i = 0; i < 64; i++) {
        int col = lane + 32 * i;
        float d = hr[col] - xr[col];
        s += d * d;
    }
#pragma unroll
    for (int o = 16; o; o >>= 1) s += __shfl_xor_sync(0xffffffffu, s, o);
    if (lane == 0) {
        float recon = s * (1.0f / 2048.0f);
        out_loss[row] = vloss[row] + recon;
    }
    if (lane < 3) out_idx[row * 3 + lane] = (float)idx[row * 3 + lane];
}

// ---------------------------------------------------------------------------
// Launch
// ---------------------------------------------------------------------------
extern "C" void kernel_launch(void* const* d_in, const int* in_sizes, int n_in,
                              void* d_out, int out_size)
{
    const float* x      = (const float*)d_in[0];
    const float* encW1  = (const float*)d_in[1];
    const float* encb1  = (const float*)d_in[2];
    const float* encW2  = (const float*)d_in[3];
    const float* encb2  = (const float*)d_in[4];
    const float* encW3  = (const float*)d_in[5];
    const float* encb3  = (const float*)d_in[6];
    const float* ln_g   = (const float*)d_in[7];
    const float* ln_b   = (const float*)d_in[8];
    const float* cb0    = (const float*)d_in[9];
    const float* cb1    = (const float*)d_in[10];
    const float* cb2    = (const float*)d_in[11];
    const float* decW1  = (const float*)d_in[12];
    const float* decb1  = (const float*)d_in[13];
    const float* decW2  = (const float*)d_in[14];
    const float* decb2  = (const float*)d_in[15];
    const float* decW3  = (const float*)d_in[16];
    const float* decb3  = (const float*)d_in[17];

    float *h1, *h2, *res, *zq, *vloss, *cbn;
    float *w1t, *w2t, *w3t, *d1t, *d2t, *d3t;
    int* idx;
    cudaGetSymbolAddress((void**)&h1, g_h1);
    cudaGetSymbolAddress((void**)&h2, g_h2);
    cudaGetSymbolAddress((void**)&res, g_res);
    cudaGetSymbolAddress((void**)&zq, g_zq);
    cudaGetSymbolAddress((void**)&vloss, g_vloss);
    cudaGetSymbolAddress((void**)&cbn, g_cbn);
    cudaGetSymbolAddress((void**)&idx, g_idx);
    cudaGetSymbolAddress((void**)&w1t, g_w1t);
    cudaGetSymbolAddress((void**)&w2t, g_w2t);
    cudaGetSymbolAddress((void**)&w3t, g_w3t);
    cudaGetSymbolAddress((void**)&d1t, g_d1t);
    cudaGetSymbolAddress((void**)&d2t, g_d2t);
    cudaGetSymbolAddress((void**)&d3t, g_d3t);

    float* xhat     = (float*)d_out;
    float* out_loss = xhat + (size_t)BATCH * D_IN;
    float* out_idx  = out_loss + BATCH;

    const int SMEM3 = 2 * 32768;   // 64 KB -> 2 CTAs/SM
    const int SMEM1 = 2 * 16384;   // 32 KB
    cudaFuncSetAttribute((const void*)mma_gemm<3, true,  true >, cudaFuncAttributeMaxDynamicSharedMemorySize, SMEM3);
    cudaFuncSetAttribute((const void*)mma_gemm<3, false, true >, cudaFuncAttributeMaxDynamicSharedMemorySize, SMEM3);
    cudaFuncSetAttribute((const void*)mma_gemm<1, false, false>, cudaFuncAttributeMaxDynamicSharedMemorySize, SMEM1);
    cudaFuncSetAttribute((const void*)mma_gemm<1, true,  true >, cudaFuncAttributeMaxDynamicSharedMemorySize, SMEM1);
    cudaFuncSetAttribute((const void*)mma_gemm<1, false, true >, cudaFuncAttributeMaxDynamicSharedMemorySize, SMEM1);

    const dim3 blk(256);
    const dim3 tblk(32, 8);
    const int MB = BATCH / 128;          // 128
    const int warpGrid = BATCH / 8;      // 2048

    // ---- prep: transpose weights to [N,K]; codebook norms ----
    transpose_kernel<<<dim3(H1D / 32, D_IN / 32), tblk>>>(encW1, w1t, D_IN, H1D);
    transpose_kernel<<<dim3(H2D / 32, H1D / 32), tblk>>>(encW2, w2t, H1D, H2D);
    transpose_kernel<<<dim3(DLAT / 32, H2D / 32), tblk>>>(encW3, w3t, H2D, DLAT);
    transpose_kernel<<<dim3(H2D / 32, DLAT / 32), tblk>>>(decW1, d1t, DLAT, H2D);
    transpose_kernel<<<dim3(H1D / 32, H2D / 32), tblk>>>(decW2, d2t, H2D, H1D);
    transpose_kernel<<<dim3(D_IN / 32, H1D / 32), tblk>>>(decW3, d3t, H1D, D_IN);
    cbnorm_kernel<<<3 * KCODE / 8, blk>>>(cb0, cb1, cb2, cbn);

    // ---- encoder (tf32x3 split = fp32 accuracy; feeds argmin) ----
    mma_gemm<3, true,  true ><<<dim3(H1D / 128, MB), blk, SMEM3>>>(x,  w1t, encb1, h1,  H1D,  D_IN);
    mma_gemm<3, true,  true ><<<dim3(H2D / 128, MB), blk, SMEM3>>>(h1, w2t, encb2, h2,  H2D,  H1D);
    mma_gemm<3, false, true ><<<dim3(DLAT / 128, MB), blk, SMEM3>>>(h2, w3t, encb3, res, DLAT, H2D);

    ln_kernel<<<warpGrid, blk>>>(res, ln_g, ln_b);

    // ---- residual VQ: approx scores (NT=1) + exact refinement in vq_step ----
    for (int s = 0; s < 3; s++) {
        const float* cb = (s == 0) ? cb0 : (s == 1 ? cb1 : cb2);
        mma_gemm<1, false, false><<<dim3(KCODE / 128, MB), blk, SMEM1>>>(res, cb, nullptr, h1, KCODE, DLAT);
        vq_step<<<warpGrid, blk>>>(res, h1, cbn + s * KCODE, cb, zq, vloss, idx, s);
    }

    // ---- decoder (single-pass tf32; post-argmin, tolerance-safe) ----
    mma_gemm<1, true,  true ><<<dim3(H2D / 128, MB), blk, SMEM1>>>(zq, d1t, decb1, h2,   H2D,  DLAT);
    mma_gemm<1, true,  true ><<<dim3(H1D / 128, MB), blk, SMEM1>>>(h2, d2t, decb2, h1,   H1D,  H2D);
    mma_gemm<1, false, true ><<<dim3(D_IN / 128, MB), blk, SMEM1>>>(h1, d3t, decb3, xhat, D_IN, H1D);

    finalize_kernel<<<warpGrid, blk>>>(x, xhat, vloss, idx, out_loss, out_idx);
}

// round 7
// speedup vs baseline: 1.5036x; 1.3814x over previous
#include <cuda_runtime.h>
#include <cuda_fp16.h>
#include <math.h>
#include <stdint.h>

// Problem dims (fixed by the dataset)
constexpr int BATCH = 16384;
constexpr int D_IN  = 2048;
constexpr int H1D   = 1024;
constexpr int H2D   = 512;
constexpr int DLAT  = 256;
constexpr int KCODE = 1024;

// fp16 staging scales (powers of 2; exact rescale in epilogue)
constexpr float SA = 16.0f;
constexpr float SB = 32.0f;
constexpr float INVS = 1.0f / (16.0f * 32.0f);

// ---------------------------------------------------------------------------
// Scratch (allocation-free contract: __device__ globals)
// ---------------------------------------------------------------------------
__device__ float g_h1[(size_t)BATCH * H1D];     // enc h1 / VQ scores / dec h1
__device__ float g_h2[(size_t)BATCH * H2D];     // enc h2 / dec h2
__device__ float g_res[(size_t)BATCH * DLAT];   // z after LN, then running residual
__device__ float g_zq[(size_t)BATCH * DLAT];    // z_q_total
__device__ float g_vloss[BATCH];
__device__ int   g_idx[BATCH * 3];
__device__ float g_cbn[3 * KCODE];
// transposed weights, [N,K] row-major (K-major rows for the B operand)
__device__ float g_w1t[(size_t)H1D * D_IN];
__device__ float g_w2t[(size_t)H2D * H1D];
__device__ float g_w3t[(size_t)DLAT * H2D];
__device__ float g_d1t[(size_t)H2D * DLAT];
__device__ float g_d2t[(size_t)H1D * H2D];
__device__ float g_d3t[(size_t)D_IN * H1D];

// ---------------------------------------------------------------------------
// Helpers
// ---------------------------------------------------------------------------
__device__ __forceinline__ uint32_t pack_h2(__half a, __half b) {
    __half2 h = __halves2half2(a, b);
    return *(uint32_t*)&h;
}

// split x,y (pre-scaled) into packed fp16 hi and lo half2
__device__ __forceinline__ void split2(float x, float y,
                                       uint32_t& hi, uint32_t& lo) {
    __half hx = __float2half_rn(x), hy = __float2half_rn(y);
    __half lx = __float2half_rn(x - __half2float(hx));
    __half ly = __float2half_rn(y - __half2float(hy));
    hi = pack_h2(hx, hy);
    lo = pack_h2(lx, ly);
}

__device__ __forceinline__ uint32_t cvt2(float x, float y) {
    return pack_h2(__float2half_rn(x), __float2half_rn(y));
}

// m16n8k16 fp16 MMA (row.col), fp32 accumulate
__device__ __forceinline__ void mma16(float d[4], const uint32_t a[4],
                                      const uint32_t b[2]) {
    asm volatile(
        "mma.sync.aligned.m16n8k16.row.col.f32.f16.f16.f32 "
        "{%0,%1,%2,%3}, {%4,%5,%6,%7}, {%8,%9}, {%0,%1,%2,%3};\n"
        : "+f"(d[0]), "+f"(d[1]), "+f"(d[2]), "+f"(d[3])
        : "r"(a[0]), "r"(a[1]), "r"(a[2]), "r"(a[3]),
          "r"(b[0]), "r"(b[1]));
}

// fp16 tile: [128 rows][16 halves] = 32B rows.
// Swizzle: 16B group m at row r stored at m ^ ((r>>2)&1). Same flip for r and r+8.
// A fragment (16x16): reg0=(r,2q|2q+1) reg1=(r+8,..) reg2=(r,2q+8|9) reg3=(r+8,..)
__device__ __forceinline__ void ld_afrag_h(const char* base, int mt, int lane,
                                           uint32_t a[4]) {
    uint32_t row = mt * 16 + (lane >> 2);
    uint32_t fl  = ((row >> 2) & 1u) << 4;
    uint32_t c0  = ((uint32_t)(lane & 3) * 4) ^ fl;
    const char* p0 = base + row * 32;
    const char* p1 = p0 + 8 * 32;
    a[0] = *(const uint32_t*)(p0 + c0);
    a[1] = *(const uint32_t*)(p1 + c0);
    a[2] = *(const uint32_t*)(p0 + (c0 ^ 16u));
    a[3] = *(const uint32_t*)(p1 + (c0 ^ 16u));
}

// B fragment (16x8, B^T stored [n][k]): reg0=(n, k=2q|2q+1) reg1=(n, k+8|9)
__device__ __forceinline__ void ld_bfrag_h(const char* base, int nt, int lane,
                                           uint32_t b[2]) {
    uint32_t row = nt * 8 + (lane >> 2);
    uint32_t fl  = ((row >> 2) & 1u) << 4;
    uint32_t c0  = ((uint32_t)(lane & 3) * 4) ^ fl;
    const char* p = base + row * 32;
    b[0] = *(const uint32_t*)(p + c0);
    b[1] = *(const uint32_t*)(p + (c0 ^ 16u));
}

// ---------------------------------------------------------------------------
// fp16 mma.sync GEMM: C[M,N] = act((A[M,K] @ B^T) + bias)
//   Staging scales A by SA and B by SB (fp16 range), epilogue rescales by INVS.
//   NTERMS==3: fp16 2-way split, products hi*hi + hi*lo + lo*hi (~2^-22 acc)
//   NTERMS==1: single-pass fp16 (2^-11, same as tf32 single)
// Tile 128x128, BK=16 (one k16 MMA step/chunk), 256 threads, 8 warps (2m x 4n).
// Stage: NT3 = Ah,Bh,Al,Bl 4KB each = 16KB; NT1 = 8KB. Double-buffered.
// ---------------------------------------------------------------------------
template <int NTERMS, bool RELU, bool HASBIAS>
__global__ __launch_bounds__(256, 2)
void mma_gemm_h(const float* __restrict__ A, const float* __restrict__ B,
                const float* __restrict__ bias, float* __restrict__ C,
                int N, int Kd)
{
    extern __shared__ char smem[];
    constexpr int TILEB = 4096;
    constexpr int STAGE = (NTERMS == 3) ? 16384 : 8192;

    const int tid  = threadIdx.x;
    const int wid  = tid >> 5;
    const int lane = tid & 31;
    const int wm   = wid & 1;       // 0..1 -> 64 rows
    const int wn   = wid >> 1;      // 0..3 -> 32 cols

    const int nk = Kd >> 4;         // BK=16 chunks
    const float* Ag = A + (size_t)(blockIdx.y * 128) * Kd;
    const float* Bg = B + (size_t)(blockIdx.x * 128) * Kd;

    // staging role: thread -> (row r, 8-float half hf of the 16-wide k chunk)
    const int r  = tid >> 1;
    const int hf = tid & 1;
    const uint32_t soff = (uint32_t)r * 32 +
                          ((uint32_t)(hf ^ ((r >> 2) & 1))) * 16;

    float acc[4][4][4];
#pragma unroll
    for (int i = 0; i < 4; i++)
#pragma unroll
        for (int j = 0; j < 4; j++)
#pragma unroll
            for (int q = 0; q < 4; q++) acc[i][j][q] = 0.0f;

    float4 va[2], vb[2];

    auto ldg = [&](int k0) {
        const float4* pa = (const float4*)(Ag + (size_t)r * Kd + k0 * 16 + hf * 8);
        const float4* pb = (const float4*)(Bg + (size_t)r * Kd + k0 * 16 + hf * 8);
        va[0] = pa[0]; va[1] = pa[1];
        vb[0] = pb[0]; vb[1] = pb[1];
    };

    auto stage_store = [&](int s) {
        char* st = smem + s * STAGE;
        if (NTERMS == 3) {
            uint4 ha, la, hb, lb;
            split2(SA * va[0].x, SA * va[0].y, ha.x, la.x);
            split2(SA * va[0].z, SA * va[0].w, ha.y, la.y);
            split2(SA * va[1].x, SA * va[1].y, ha.z, la.z);
            split2(SA * va[1].z, SA * va[1].w, ha.w, la.w);
            split2(SB * vb[0].x, SB * vb[0].y, hb.x, lb.x);
            split2(SB * vb[0].z, SB * vb[0].w, hb.y, lb.y);
            split2(SB * vb[1].x, SB * vb[1].y, hb.z, lb.z);
            split2(SB * vb[1].z, SB * vb[1].w, hb.w, lb.w);
            *(uint4*)(st + soff)             = ha;
            *(uint4*)(st + TILEB + soff)     = hb;
            *(uint4*)(st + 2 * TILEB + soff) = la;
            *(uint4*)(st + 3 * TILEB + soff) = lb;
        } else {
            uint4 ha, hb;
            ha.x = cvt2(SA * va[0].x, SA * va[0].y);
            ha.y = cvt2(SA * va[0].z, SA * va[0].w);
            ha.z = cvt2(SA * va[1].x, SA * va[1].y);
            ha.w = cvt2(SA * va[1].z, SA * va[1].w);
            hb.x = cvt2(SB * vb[0].x, SB * vb[0].y);
            hb.y = cvt2(SB * vb[0].z, SB * vb[0].w);
            hb.z = cvt2(SB * vb[1].x, SB * vb[1].y);
            hb.w = cvt2(SB * vb[1].z, SB * vb[1].w);
            *(uint4*)(st + soff)         = ha;
            *(uint4*)(st + TILEB + soff) = hb;
        }
    };

    ldg(0);
    stage_store(0);
    __syncthreads();

    for (int k0 = 0; k0 < nk; k0++) {
        if (k0 + 1 < nk) ldg(k0 + 1);

        const char* st = smem + (k0 & 1) * STAGE;
        uint32_t bh[4][2], bl[4][2];
#pragma unroll
        for (int nt = 0; nt < 4; nt++) {
            ld_bfrag_h(st + TILEB, wn * 4 + nt, lane, bh[nt]);
            if (NTERMS == 3)
                ld_bfrag_h(st + 3 * TILEB, wn * 4 + nt, lane, bl[nt]);
        }
#pragma unroll
        for (int mt = 0; mt < 4; mt++) {
            uint32_t ah[4], al[4];
            ld_afrag_h(st, wm * 4 + mt, lane, ah);
            if (NTERMS == 3)
                ld_afrag_h(st + 2 * TILEB, wm * 4 + mt, lane, al);
#pragma unroll
            for (int nt = 0; nt < 4; nt++) {
                mma16(acc[mt][nt], ah, bh[nt]);
                if (NTERMS == 3) {
                    mma16(acc[mt][nt], ah, bl[nt]);
                    mma16(acc[mt][nt], al, bh[nt]);
                }
            }
        }

        if (k0 + 1 < nk) stage_store((k0 + 1) & 1);
        __syncthreads();
    }

    // ---- epilogue (rescale by INVS, then bias/ReLU) ----
    const int row0 = blockIdx.y * 128 + wm * 64 + (lane >> 2);
    const int col0 = blockIdx.x * 128 + wn * 32 + (lane & 3) * 2;
#pragma unroll
    for (int mt = 0; mt < 4; mt++) {
#pragma unroll
        for (int nt = 0; nt < 4; nt++) {
            int rr = row0 + mt * 16;
            int cc = col0 + nt * 8;
            float b0 = 0.f, b1 = 0.f;
            if (HASBIAS) { b0 = __ldg(bias + cc); b1 = __ldg(bias + cc + 1); }
            float2 v0, v1;
            v0.x = acc[mt][nt][0] * INVS + b0; v0.y = acc[mt][nt][1] * INVS + b1;
            v1.x = acc[mt][nt][2] * INVS + b0; v1.y = acc[mt][nt][3] * INVS + b1;
            if (RELU) {
                v0.x = fmaxf(v0.x, 0.f); v0.y = fmaxf(v0.y, 0.f);
                v1.x = fmaxf(v1.x, 0.f); v1.y = fmaxf(v1.y, 0.f);
            }
            *(float2*)(C + (size_t)rr * N + cc)       = v0;
            *(float2*)(C + (size_t)(rr + 8) * N + cc) = v1;
        }
    }
}

// ---------------------------------------------------------------------------
// Tiled transpose: W[K,N] -> T[N,K]
// ---------------------------------------------------------------------------
__global__ __launch_bounds__(256)
void transpose_kernel(const float* __restrict__ W, float* __restrict__ T,
                      int K, int N)
{
    __shared__ float tile[32][33];
    int n0 = blockIdx.x * 32;
    int k0 = blockIdx.y * 32;
#pragma unroll
    for (int i = 0; i < 32; i += 8)
        tile[threadIdx.y + i][threadIdx.x] =
            W[(size_t)(k0 + threadIdx.y + i) * N + n0 + threadIdx.x];
    __syncthreads();
#pragma unroll
    for (int i = 0; i < 32; i += 8)
        T[(size_t)(n0 + threadIdx.y + i) * K + k0 + threadIdx.x] =
            tile[threadIdx.x][threadIdx.y + i];
}

// ---------------------------------------------------------------------------
// LayerNorm over DLAT=256, warp per row
// ---------------------------------------------------------------------------
__global__ __launch_bounds__(256)
void ln_kernel(float* __restrict__ z, const float* __restrict__ g,
               const float* __restrict__ b)
{
    int row  = blockIdx.x * 8 + (threadIdx.x >> 5);
    int lane = threadIdx.x & 31;
    float* zr = z + (size_t)row * DLAT;

    float v[8];
    float s = 0.f;
#pragma unroll
    for (int i = 0; i < 8; i++) { v[i] = zr[lane + 32 * i]; s += v[i]; }
#pragma unroll
    for (int o = 16; o; o >>= 1) s += __shfl_xor_sync(0xffffffffu, s, o);
    float mu = s * (1.0f / 256.0f);

    float s2 = 0.f;
#pragma unroll
    for (int i = 0; i < 8; i++) { float d = v[i] - mu; s2 += d * d; }
#pragma unroll
    for (int o = 16; o; o >>= 1) s2 += __shfl_xor_sync(0xffffffffu, s2, o);
    float var = s2 * (1.0f / 256.0f);
    float rs  = 1.0f / sqrtf(var + 1e-5f);

#pragma unroll
    for (int i = 0; i < 8; i++) {
        int col = lane + 32 * i;
        zr[col] = (v[i] - mu) * rs * g[col] + b[col];
    }
}

// ---------------------------------------------------------------------------
// Codebook row norms: warp per code
// ---------------------------------------------------------------------------
__global__ __launch_bounds__(256)
void cbnorm_kernel(const float* __restrict__ cb0, const float* __restrict__ cb1,
                   const float* __restrict__ cb2, float* __restrict__ cbn)
{
    int code = blockIdx.x * 8 + (threadIdx.x >> 5);
    int lane = threadIdx.x & 31;
    const float* cb = (code < KCODE) ? cb0 : (code < 2 * KCODE ? cb1 : cb2);
    const float* c  = cb + (size_t)(code & (KCODE - 1)) * DLAT;
    float s = 0.f;
#pragma unroll
    for (int i = 0; i < 8; i++) { float v = c[lane + 32 * i]; s += v * v; }
#pragma unroll
    for (int o = 16; o; o >>= 1) s += __shfl_xor_sync(0xffffffffu, s, o);
    if (lane == 0) cbn[code] = s;
}

// ---------------------------------------------------------------------------
// Fused VQ step with exact refinement (approx scores -> exact fp32 recheck
// of all candidates within MARGIN). Warp per row.
// ---------------------------------------------------------------------------
constexpr float VQ_MARGIN = 0.05f;

__global__ __launch_bounds__(256)
void vq_step(float* __restrict__ res, const float* __restrict__ scores,
             const float* __restrict__ cbn, const float* __restrict__ cb,
             float* __restrict__ zq, float* __restrict__ vloss,
             int* __restrict__ idx_out, int stage)
{
    int row  = blockIdx.x * 8 + (threadIdx.x >> 5);
    int lane = threadIdx.x & 31;

    float* r = res + (size_t)row * DLAT;
    float rv[8];
    float s = 0.f;
#pragma unroll
    for (int i = 0; i < 8; i++) { rv[i] = r[lane + 32 * i]; s += rv[i] * rv[i]; }
#pragma unroll
    for (int o = 16; o; o >>= 1) s += __shfl_xor_sync(0xffffffffu, s, o);
    const float rnorm = s;

    // pass 1: approximate min distance (value only)
    const float* sr = scores + (size_t)row * KCODE;
    float amin = INFINITY;
    float dv[32];
#pragma unroll 4
    for (int j = 0; j < 32; j++) {
        int n = lane + 32 * j;
        float d = (rnorm - 2.0f * sr[n]) + cbn[n];
        dv[j] = d;
        amin = fminf(amin, d);
    }
#pragma unroll
    for (int o = 16; o; o >>= 1)
        amin = fminf(amin, __shfl_xor_sync(0xffffffffu, amin, o));

    // pass 2: candidate mask per lane (bit j <-> code lane + 32j)
    const float thresh = amin + VQ_MARGIN;
    uint32_t cmask = 0;
#pragma unroll
    for (int j = 0; j < 32; j++)
        if (dv[j] <= thresh) cmask |= (1u << j);

    // warp-cooperative exact refinement, one candidate per iteration
    float bestv = INFINITY;
    int   bestn = KCODE;
    for (;;) {
        uint32_t ball = __ballot_sync(0xffffffffu, cmask != 0);
        if (!ball) break;
        int src = __ffs(ball) - 1;
        uint32_t m = __shfl_sync(0xffffffffu, cmask, src);
        int j = __ffs(m) - 1;
        if (lane == src) cmask &= cmask - 1;   // clear lowest bit
        int n = src + 32 * j;

        const float* c = cb + (size_t)n * DLAT;
        float dot = 0.f;
#pragma unroll
        for (int i = 0; i < 8; i++) dot += rv[i] * c[lane + 32 * i];
#pragma unroll
        for (int o = 16; o; o >>= 1) dot += __shfl_xor_sync(0xffffffffu, dot, o);

        float d = (rnorm - 2.0f * dot) + cbn[n];
        if (d < bestv || (d == bestv && n < bestn)) { bestv = d; bestn = n; }
    }
    const int bi = bestn;
    if (lane == 0) idx_out[row * 3 + stage] = bi;

    // straight-through update (replicates JAX numerics exactly)
    const float* c = cb + (size_t)bi * DLAT;
    float* q = zq + (size_t)row * DLAT;
    float se = 0.f;
#pragma unroll
    for (int i = 0; i < 8; i++) {
        int col = lane + 32 * i;
        float ev = c[col];
        float diff = rv[i] - ev;
        se += diff * diff;
        float t   = ev - rv[i];      // sg(e - r)
        float zqe = rv[i] + t;       // straight-through z_q
        r[col] = rv[i] - zqe;        // residual - sg(z_q)
        q[col] = (stage == 0) ? zqe : (q[col] + zqe);
    }
#pragma unroll
    for (int o = 16; o; o >>= 1) se += __shfl_xor_sync(0xffffffffu, se, o);
    if (lane == 0) {
        float m = se * (1.0f / 256.0f);
        float l = m + 0.25f * m;
        vloss[row] = (stage == 0) ? l : (vloss[row] + l);
    }
}

// ---------------------------------------------------------------------------
// Finalize: recon loss, total loss, idx -> float
// ---------------------------------------------------------------------------
__global__ __launch_bounds__(256)
void finalize_kernel(const float* __restrict__ x, const float* __restrict__ xhat,
                     const float* __restrict__ vloss, const int* __restrict__ idx,
                     float* __restrict__ out_loss, float* __restrict__ out_idx)
{
    int row  = blockIdx.x * 8 + (threadIdx.x >> 5);
    int lane = threadIdx.x & 31;

    const float* xr = x    + (size_t)row * D_IN;
    const float* hr = xhat + (size_t)row * D_IN;
    float s = 0.f;
#pragma unroll 8
    for (int i = 0; i < 64; i++) {
        int col = lane + 32 * i;
        float d = hr[col] - xr[col];
        s += d * d;
    }
#pragma unroll
    for (int o = 16; o; o >>= 1) s += __shfl_xor_sync(0xffffffffu, s, o);
    if (lane == 0) {
        float recon = s * (1.0f / 2048.0f);
        out_loss[row] = vloss[row] + recon;
    }
    if (lane < 3) out_idx[row * 3 + lane] = (float)idx[row * 3 + lane];
}

// ---------------------------------------------------------------------------
// Launch
// ---------------------------------------------------------------------------
extern "C" void kernel_launch(void* const* d_in, const int* in_sizes, int n_in,
                              void* d_out, int out_size)
{
    const float* x      = (const float*)d_in[0];
    const float* encW1  = (const float*)d_in[1];
    const float* encb1  = (const float*)d_in[2];
    const float* encW2  = (const float*)d_in[3];
    const float* encb2  = (const float*)d_in[4];
    const float* encW3  = (const float*)d_in[5];
    const float* encb3  = (const float*)d_in[6];
    const float* ln_g   = (const float*)d_in[7];
    const float* ln_b   = (const float*)d_in[8];
    const float* cb0    = (const float*)d_in[9];
    const float* cb1    = (const float*)d_in[10];
    const float* cb2    = (const float*)d_in[11];
    const float* decW1  = (const float*)d_in[12];
    const float* decb1  = (const float*)d_in[13];
    const float* decW2  = (const float*)d_in[14];
    const float* decb2  = (const float*)d_in[15];
    const float* decW3  = (const float*)d_in[16];
    const float* decb3  = (const float*)d_in[17];

    float *h1, *h2, *res, *zq, *vloss, *cbn;
    float *w1t, *w2t, *w3t, *d1t, *d2t, *d3t;
    int* idx;
    cudaGetSymbolAddress((void**)&h1, g_h1);
    cudaGetSymbolAddress((void**)&h2, g_h2);
    cudaGetSymbolAddress((void**)&res, g_res);
    cudaGetSymbolAddress((void**)&zq, g_zq);
    cudaGetSymbolAddress((void**)&vloss, g_vloss);
    cudaGetSymbolAddress((void**)&cbn, g_cbn);
    cudaGetSymbolAddress((void**)&idx, g_idx);
    cudaGetSymbolAddress((void**)&w1t, g_w1t);
    cudaGetSymbolAddress((void**)&w2t, g_w2t);
    cudaGetSymbolAddress((void**)&w3t, g_w3t);
    cudaGetSymbolAddress((void**)&d1t, g_d1t);
    cudaGetSymbolAddress((void**)&d2t, g_d2t);
    cudaGetSymbolAddress((void**)&d3t, g_d3t);

    float* xhat     = (float*)d_out;
    float* out_loss = xhat + (size_t)BATCH * D_IN;
    float* out_idx  = out_loss + BATCH;

    const int SMEM3 = 2 * 16384;   // 32 KB
    const int SMEM1 = 2 * 8192;    // 16 KB
    cudaFuncSetAttribute((const void*)mma_gemm_h<3, true,  true >, cudaFuncAttributeMaxDynamicSharedMemorySize, SMEM3);
    cudaFuncSetAttribute((const void*)mma_gemm_h<3, false, true >, cudaFuncAttributeMaxDynamicSharedMemorySize, SMEM3);
    cudaFuncSetAttribute((const void*)mma_gemm_h<1, false, false>, cudaFuncAttributeMaxDynamicSharedMemorySize, SMEM1);
    cudaFuncSetAttribute((const void*)mma_gemm_h<1, true,  true >, cudaFuncAttributeMaxDynamicSharedMemorySize, SMEM1);
    cudaFuncSetAttribute((const void*)mma_gemm_h<1, false, true >, cudaFuncAttributeMaxDynamicSharedMemorySize, SMEM1);

    const dim3 blk(256);
    const dim3 tblk(32, 8);
    const int MB = BATCH / 128;          // 128
    const int warpGrid = BATCH / 8;      // 2048

    // ---- prep: transpose weights to [N,K]; codebook norms ----
    transpose_kernel<<<dim3(H1D / 32, D_IN / 32), tblk>>>(encW1, w1t, D_IN, H1D);
    transpose_kernel<<<dim3(H2D / 32, H1D / 32), tblk>>>(encW2, w2t, H1D, H2D);
    transpose_kernel<<<dim3(DLAT / 32, H2D / 32), tblk>>>(encW3, w3t, H2D, DLAT);
    transpose_kernel<<<dim3(H2D / 32, DLAT / 32), tblk>>>(decW1, d1t, DLAT, H2D);
    transpose_kernel<<<dim3(H1D / 32, H2D / 32), tblk>>>(decW2, d2t, H2D, H1D);
    transpose_kernel<<<dim3(D_IN / 32, H1D / 32), tblk>>>(decW3, d3t, H1D, D_IN);
    cbnorm_kernel<<<3 * KCODE / 8, blk>>>(cb0, cb1, cb2, cbn);

    // ---- encoder (fp16 split x3 ~ fp32 accuracy; feeds argmin) ----
    mma_gemm_h<3, true,  true ><<<dim3(H1D / 128, MB), blk, SMEM3>>>(x,  w1t, encb1, h1,  H1D,  D_IN);
    mma_gemm_h<3, true,  true ><<<dim3(H2D / 128, MB), blk, SMEM3>>>(h1, w2t, encb2, h2,  H2D,  H1D);
    mma_gemm_h<3, false, true ><<<dim3(DLAT / 128, MB), blk, SMEM3>>>(h2, w3t, encb3, res, DLAT, H2D);

    ln_kernel<<<warpGrid, blk>>>(res, ln_g, ln_b);

    // ---- residual VQ: approx scores (fp16 single) + exact refinement ----
    for (int s = 0; s < 3; s++) {
        const float* cb = (s == 0) ? cb0 : (s == 1 ? cb1 : cb2);
        mma_gemm_h<1, false, false><<<dim3(KCODE / 128, MB), blk, SMEM1>>>(res, cb, nullptr, h1, KCODE, DLAT);
        vq_step<<<warpGrid, blk>>>(res, h1, cbn + s * KCODE, cb, zq, vloss, idx, s);
    }

    // ---- decoder (fp16 single-pass; post-argmin, tolerance-safe) ----
    mma_gemm_h<1, true,  true ><<<dim3(H2D / 128, MB), blk, SMEM1>>>(zq, d1t, decb1, h2,   H2D,  DLAT);
    mma_gemm_h<1, true,  true ><<<dim3(H1D / 128, MB), blk, SMEM1>>>(h2, d2t, decb2, h1,   H1D,  H2D);
    mma_gemm_h<1, false, true ><<<dim3(D_IN / 128, MB), blk, SMEM1>>>(h1, d3t, decb3, xhat, D_IN, H1D);

    finalize_kernel<<<warpGrid, blk>>>(x, xhat, vloss, idx, out_loss, out_idx);
}

// round 8
// speedup vs baseline: 1.8885x; 1.2559x over previous
#include <cuda_runtime.h>
#include <cuda_fp16.h>
#include <math.h>
#include <stdint.h>

// Problem dims (fixed by the dataset)
constexpr int BATCH = 16384;
constexpr int D_IN  = 2048;
constexpr int H1D   = 1024;
constexpr int H2D   = 512;
constexpr int DLAT  = 256;
constexpr int KCODE = 1024;

// fp16 staging scales (powers of 2; exact rescale in epilogue)
constexpr float SA = 16.0f;
constexpr float SB = 32.0f;
constexpr float INVS = 1.0f / (16.0f * 32.0f);

// ---------------------------------------------------------------------------
// Scratch (allocation-free contract: __device__ globals)
// ---------------------------------------------------------------------------
__device__ float g_h1[(size_t)BATCH * H1D];     // enc h1 / VQ scores / dec h1
__device__ float g_h2[(size_t)BATCH * H2D];     // enc h2 / dec h2
__device__ float g_res[(size_t)BATCH * DLAT];   // z after LN, then running residual
__device__ float g_zq[(size_t)BATCH * DLAT];    // z_q_total
__device__ float g_vloss[BATCH];
__device__ int   g_idx[BATCH * 3];
__device__ float g_cbn[3 * KCODE];
// pre-split fp16 weights, [N,K] row-major, scaled by SB
__device__ __half g_w1h[(size_t)H1D * D_IN], g_w1l[(size_t)H1D * D_IN];
__device__ __half g_w2h[(size_t)H2D * H1D], g_w2l[(size_t)H2D * H1D];
__device__ __half g_w3h[(size_t)DLAT * H2D], g_w3l[(size_t)DLAT * H2D];
__device__ __half g_d1h[(size_t)H2D * DLAT], g_d1l[(size_t)H2D * DLAT];
__device__ __half g_d2h[(size_t)H1D * H2D], g_d2l[(size_t)H1D * H2D];
__device__ __half g_d3h[(size_t)D_IN * H1D], g_d3l[(size_t)D_IN * H1D];
__device__ __half g_cbh[(size_t)3 * KCODE * DLAT];   // hi-only, scaled by SB

// ---------------------------------------------------------------------------
// Helpers
// ---------------------------------------------------------------------------
__device__ __forceinline__ uint32_t smem_u32(const void* p) {
    uint32_t a;
    asm("{ .reg .u64 t; cvta.to.shared.u64 t, %1; cvt.u32.u64 %0, t; }"
        : "=r"(a) : "l"(p));
    return a;
}

__device__ __forceinline__ uint32_t pack_h2(__half a, __half b) {
    __half2 h = __halves2half2(a, b);
    return *(uint32_t*)&h;
}

// split x,y (pre-scaled) into packed fp16 hi and lo half2
__device__ __forceinline__ void split2(float x, float y,
                                       uint32_t& hi, uint32_t& lo) {
    __half hx = __float2half_rn(x), hy = __float2half_rn(y);
    __half lx = __float2half_rn(x - __half2float(hx));
    __half ly = __float2half_rn(y - __half2float(hy));
    hi = pack_h2(hx, hy);
    lo = pack_h2(lx, ly);
}

// m16n8k16 fp16 MMA (row.col), fp32 accumulate
__device__ __forceinline__ void mma16(float d[4], const uint32_t a[4],
                                      const uint32_t b[2]) {
    asm volatile(
        "mma.sync.aligned.m16n8k16.row.col.f32.f16.f16.f32 "
        "{%0,%1,%2,%3}, {%4,%5,%6,%7}, {%8,%9}, {%0,%1,%2,%3};\n"
        : "+f"(d[0]), "+f"(d[1]), "+f"(d[2]), "+f"(d[3])
        : "r"(a[0]), "r"(a[1]), "r"(a[2]), "r"(a[3]),
          "r"(b[0]), "r"(b[1]));
}

__device__ __forceinline__ void ldsm4(uint32_t& r0, uint32_t& r1,
                                      uint32_t& r2, uint32_t& r3, uint32_t addr) {
    asm volatile("ldmatrix.sync.aligned.m8n8.x4.shared.b16 {%0,%1,%2,%3}, [%4];"
                 : "=r"(r0), "=r"(r1), "=r"(r2), "=r"(r3) : "r"(addr));
}

// fp16 tile: [128 rows][16 halves] = 32B rows.
// 16B group g of row r stored at group (g ^ ((r>>2)&1)).  Conflict-free for
// both the staging STS.128 and every 8-address ldmatrix phase.
__device__ __forceinline__ uint32_t tile_addr(uint32_t row, uint32_t g) {
    return row * 32 + ((g ^ ((row >> 2) & 1u)) << 4);
}

// ---------------------------------------------------------------------------
// fp16 mma.sync GEMM with pre-split B: C = act((A @ B^T)*INVS + bias)
//   A fp32 [M,K]; Bhi/Blo fp16 [N,K] pre-scaled by SB.
//   NTERMS==3: A split (hi+lo) x B (hi+lo), products hh + hl + lh
//   NTERMS==1: single-pass (A rounded, Bhi)
// Tile 128x128, BK=16, 256 threads, 8 warps (2m x 4n).
// Stage: NT3 = Ah,Bh,Al,Bl 4KB each = 16KB; NT1 = 8KB. Double-buffered.
// Fragments via ldmatrix.x4.
// ---------------------------------------------------------------------------
template <int NTERMS, bool RELU, bool HASBIAS>
__global__ __launch_bounds__(256, 2)
void mma_gemm_h(const float* __restrict__ A, const __half* __restrict__ Bhi,
                const __half* __restrict__ Blo, const float* __restrict__ bias,
                float* __restrict__ C, int N, int Kd)
{
    extern __shared__ char smem[];
    const uint32_t smb = smem_u32(smem);
    constexpr int TILEB = 4096;
    constexpr int STAGE = (NTERMS == 3) ? 16384 : 8192;

    const int tid  = threadIdx.x;
    const int wid  = tid >> 5;
    const int lane = tid & 31;
    const int wm   = wid & 1;       // 0..1 -> 64 rows
    const int wn   = wid >> 1;      // 0..3 -> 32 cols

    const int nk = Kd >> 4;         // BK=16 chunks
    const float* Ag  = A   + (size_t)(blockIdx.y * 128) * Kd;
    const __half* Bh = Bhi + (size_t)(blockIdx.x * 128) * Kd;
    const __half* Bl = (NTERMS == 3) ? Blo + (size_t)(blockIdx.x * 128) * Kd : nullptr;

    // staging role: thread -> (row r, 8-element group hf of the 16-wide chunk)
    const int r  = tid >> 1;
    const int hf = tid & 1;
    const uint32_t soff = tile_addr((uint32_t)r, (uint32_t)hf);

    // ldmatrix per-lane address offsets (within a tile)
    // A: matrices (blk0,g0),(blk1,g0),(blk0,g1),(blk1,g1); blk = +8 rows
    const uint32_t amat = (uint32_t)lane >> 3;
    const uint32_t arow_l = (uint32_t)(lane & 7) + ((amat & 1u) << 3);  // + mt*16 + wm*64
    const uint32_t ag = amat >> 1;
    // B: matrices (nt_e,g0),(nt_e,g1),(nt_o,g0),(nt_o,g1); nt pair base p
    const uint32_t bmat = (uint32_t)lane >> 3;
    const uint32_t brow_l = (uint32_t)(lane & 7) + ((bmat >> 1) << 3);  // + wn*32 + p*16
    const uint32_t bg = bmat & 1u;

    float acc[4][4][4];
#pragma unroll
    for (int i = 0; i < 4; i++)
#pragma unroll
        for (int j = 0; j < 4; j++)
#pragma unroll
            for (int q = 0; q < 4; q++) acc[i][j][q] = 0.0f;

    float4 va[2];
    uint4 vbh, vbl;

    auto ldg = [&](int k0) {
        const float4* pa = (const float4*)(Ag + (size_t)r * Kd + k0 * 16 + hf * 8);
        va[0] = pa[0]; va[1] = pa[1];
        vbh = *(const uint4*)(Bh + (size_t)r * Kd + k0 * 16 + hf * 8);
        if (NTERMS == 3)
            vbl = *(const uint4*)(Bl + (size_t)r * Kd + k0 * 16 + hf * 8);
    };

    auto stage_store = [&](int s) {
        char* st = smem + s * STAGE;
        uint4 ha;
        split2(SA * va[0].x, SA * va[0].y, ha.x, ha.x);  // placeholder init
        if (NTERMS == 3) {
            uint4 la;
            split2(SA * va[0].x, SA * va[0].y, ha.x, la.x);
            split2(SA * va[0].z, SA * va[0].w, ha.y, la.y);
            split2(SA * va[1].x, SA * va[1].y, ha.z, la.z);
            split2(SA * va[1].z, SA * va[1].w, ha.w, la.w);
            *(uint4*)(st + soff)             = ha;
            *(uint4*)(st + TILEB + soff)     = vbh;
            *(uint4*)(st + 2 * TILEB + soff) = la;
            *(uint4*)(st + 3 * TILEB + soff) = vbl;
        } else {
            ha.x = pack_h2(__float2half_rn(SA * va[0].x), __float2half_rn(SA * va[0].y));
            ha.y = pack_h2(__float2half_rn(SA * va[0].z), __float2half_rn(SA * va[0].w));
            ha.z = pack_h2(__float2half_rn(SA * va[1].x), __float2half_rn(SA * va[1].y));
            ha.w = pack_h2(__float2half_rn(SA * va[1].z), __float2half_rn(SA * va[1].w));
            *(uint4*)(st + soff)         = ha;
            *(uint4*)(st + TILEB + soff) = vbh;
        }
    };

    ldg(0);
    stage_store(0);
    __syncthreads();

    for (int k0 = 0; k0 < nk; k0++) {
        if (k0 + 1 < nk) ldg(k0 + 1);

        const uint32_t stb = smb + (uint32_t)((k0 & 1) * STAGE);

        // B fragments: 2 ldmatrix.x4 (hi), +2 (lo)
        uint32_t bhf[4][2], blf[4][2];
#pragma unroll
        for (int p = 0; p < 2; p++) {
            uint32_t nrow = (uint32_t)(wn * 32 + p * 16) + brow_l;
            uint32_t ba = stb + TILEB + tile_addr(nrow, bg);
            ldsm4(bhf[p * 2][0], bhf[p * 2][1], bhf[p * 2 + 1][0], bhf[p * 2 + 1][1], ba);
            if (NTERMS == 3)
                ldsm4(blf[p * 2][0], blf[p * 2][1], blf[p * 2 + 1][0], blf[p * 2 + 1][1],
                      ba + 2 * TILEB);
        }
#pragma unroll
        for (int mt = 0; mt < 4; mt++) {
            uint32_t arow = (uint32_t)(wm * 64 + mt * 16) + arow_l;
            uint32_t aa = stb + tile_addr(arow, ag);
            uint32_t ah[4], al[4];
            ldsm4(ah[0], ah[1], ah[2], ah[3], aa);
            if (NTERMS == 3)
                ldsm4(al[0], al[1], al[2], al[3], aa + 2 * TILEB);
#pragma unroll
            for (int nt = 0; nt < 4; nt++) {
                mma16(acc[mt][nt], ah, bhf[nt]);
                if (NTERMS == 3) {
                    mma16(acc[mt][nt], ah, blf[nt]);
                    mma16(acc[mt][nt], al, bhf[nt]);
                }
            }
        }

        if (k0 + 1 < nk) stage_store((k0 + 1) & 1);
        __syncthreads();
    }

    // ---- epilogue (rescale by INVS, then bias/ReLU) ----
    const int row0 = blockIdx.y * 128 + wm * 64 + (lane >> 2);
    const int col0 = blockIdx.x * 128 + wn * 32 + (lane & 3) * 2;
#pragma unroll
    for (int mt = 0; mt < 4; mt++) {
#pragma unroll
        for (int nt = 0; nt < 4; nt++) {
            int rr = row0 + mt * 16;
            int cc = col0 + nt * 8;
            float b0 = 0.f, b1 = 0.f;
            if (HASBIAS) { b0 = __ldg(bias + cc); b1 = __ldg(bias + cc + 1); }
            float2 v0, v1;
            v0.x = acc[mt][nt][0] * INVS + b0; v0.y = acc[mt][nt][1] * INVS + b1;
            v1.x = acc[mt][nt][2] * INVS + b0; v1.y = acc[mt][nt][3] * INVS + b1;
            if (RELU) {
                v0.x = fmaxf(v0.x, 0.f); v0.y = fmaxf(v0.y, 0.f);
                v1.x = fmaxf(v1.x, 0.f); v1.y = fmaxf(v1.y, 0.f);
            }
            *(float2*)(C + (size_t)rr * N + cc)       = v0;
            *(float2*)(C + (size_t)(rr + 8) * N + cc) = v1;
        }
    }
}

// ---------------------------------------------------------------------------
// Prep: transpose + scale + split  W[K,N] f32 -> Thi/Tlo[N,K] half (x SB)
// ---------------------------------------------------------------------------
__global__ __launch_bounds__(256)
void transpose_convert(const float* __restrict__ W, __half* __restrict__ Thi,
                       __half* __restrict__ Tlo, int K, int N)
{
    __shared__ float tile[32][33];
    int n0 = blockIdx.x * 32;
    int k0 = blockIdx.y * 32;
#pragma unroll
    for (int i = 0; i < 32; i += 8)
        tile[threadIdx.y + i][threadIdx.x] =
            W[(size_t)(k0 + threadIdx.y + i) * N + n0 + threadIdx.x];
    __syncthreads();
#pragma unroll
    for (int i = 0; i < 32; i += 8) {
        float v = SB * tile[threadIdx.x][threadIdx.y + i];
        __half h = __float2half_rn(v);
        __half l = __float2half_rn(v - __half2float(h));
        size_t o = (size_t)(n0 + threadIdx.y + i) * K + k0 + threadIdx.x;
        Thi[o] = h;
        Tlo[o] = l;
    }
}

// Codebooks are already [N,K]; scores only need hi (NT=1).
__global__ __launch_bounds__(256)
void convert_cb_kernel(const float* __restrict__ cb0, const float* __restrict__ cb1,
                       const float* __restrict__ cb2, __half* __restrict__ out)
{
    int i = blockIdx.x * 256 + threadIdx.x;       // < 3*KCODE*DLAT
    const int S = KCODE * DLAT;
    const float* src = (i < S) ? cb0 : (i < 2 * S ? cb1 : cb2);
    out[i] = __float2half_rn(SB * src[i % S]);
}

// ---------------------------------------------------------------------------
// LayerNorm over DLAT=256, warp per row
// ---------------------------------------------------------------------------
__global__ __launch_bounds__(256)
void ln_kernel(float* __restrict__ z, const float* __restrict__ g,
               const float* __restrict__ b)
{
    int row  = blockIdx.x * 8 + (threadIdx.x >> 5);
    int lane = threadIdx.x & 31;
    float* zr = z + (size_t)row * DLAT;

    float v[8];
    float s = 0.f;
#pragma unroll
    for (int i = 0; i < 8; i++) { v[i] = zr[lane + 32 * i]; s += v[i]; }
#pragma unroll
    for (int o = 16; o; o >>= 1) s += __shfl_xor_sync(0xffffffffu, s, o);
    float mu = s * (1.0f / 256.0f);

    float s2 = 0.f;
#pragma unroll
    for (int i = 0; i < 8; i++) { float d = v[i] - mu; s2 += d * d; }
#pragma unroll
    for (int o = 16; o; o >>= 1) s2 += __shfl_xor_sync(0xffffffffu, s2, o);
    float var = s2 * (1.0f / 256.0f);
    float rs  = 1.0f / sqrtf(var + 1e-5f);

#pragma unroll
    for (int i = 0; i < 8; i++) {
        int col = lane + 32 * i;
        zr[col] = (v[i] - mu) * rs * g[col] + b[col];
    }
}

// ---------------------------------------------------------------------------
// Codebook row norms: warp per code (fp32 codebooks)
// ---------------------------------------------------------------------------
__global__ __launch_bounds__(256)
void cbnorm_kernel(const float* __restrict__ cb0, const float* __restrict__ cb1,
                   const float* __restrict__ cb2, float* __restrict__ cbn)
{
    int code = blockIdx.x * 8 + (threadIdx.x >> 5);
    int lane = threadIdx.x & 31;
    const float* cb = (code < KCODE) ? cb0 : (code < 2 * KCODE ? cb1 : cb2);
    const float* c  = cb + (size_t)(code & (KCODE - 1)) * DLAT;
    float s = 0.f;
#pragma unroll
    for (int i = 0; i < 8; i++) { float v = c[lane + 32 * i]; s += v * v; }
#pragma unroll
    for (int o = 16; o; o >>= 1) s += __shfl_xor_sync(0xffffffffu, s, o);
    if (lane == 0) cbn[code] = s;
}

// ---------------------------------------------------------------------------
// Fused VQ step with exact refinement (approx scores -> exact fp32 recheck
// of all candidates within MARGIN). Warp per row.
// ---------------------------------------------------------------------------
constexpr float VQ_MARGIN = 0.05f;

__global__ __launch_bounds__(256)
void vq_step(float* __restrict__ res, const float* __restrict__ scores,
             const float* __restrict__ cbn, const float* __restrict__ cb,
             float* __restrict__ zq, float* __restrict__ vloss,
             int* __restrict__ idx_out, int stage)
{
    int row  = blockIdx.x * 8 + (threadIdx.x >> 5);
    int lane = threadIdx.x & 31;

    float* r = res + (size_t)row * DLAT;
    float rv[8];
    float s = 0.f;
#pragma unroll
    for (int i = 0; i < 8; i++) { rv[i] = r[lane + 32 * i]; s += rv[i] * rv[i]; }
#pragma unroll
    for (int o = 16; o; o >>= 1) s += __shfl_xor_sync(0xffffffffu, s, o);
    const float rnorm = s;

    // pass 1: approximate min distance (value only)
    const float* sr = scores + (size_t)row * KCODE;
    float amin = INFINITY;
    float dv[32];
#pragma unroll 4
    for (int j = 0; j < 32; j++) {
        int n = lane + 32 * j;
        float d = (rnorm - 2.0f * sr[n]) + cbn[n];
        dv[j] = d;
        amin = fminf(amin, d);
    }
#pragma unroll
    for (int o = 16; o; o >>= 1)
        amin = fminf(amin, __shfl_xor_sync(0xffffffffu, amin, o));

    // pass 2: candidate mask per lane (bit j <-> code lane + 32j)
    const float thresh = amin + VQ_MARGIN;
    uint32_t cmask = 0;
#pragma unroll
    for (int j = 0; j < 32; j++)
        if (dv[j] <= thresh) cmask |= (1u << j);

    // warp-cooperative exact refinement, one candidate per iteration
    float bestv = INFINITY;
    int   bestn = KCODE;
    for (;;) {
        uint32_t ball = __ballot_sync(0xffffffffu, cmask != 0);
        if (!ball) break;
        int src = __ffs(ball) - 1;
        uint32_t m = __shfl_sync(0xffffffffu, cmask, src);
        int j = __ffs(m) - 1;
        if (lane == src) cmask &= cmask - 1;   // clear lowest bit
        int n = src + 32 * j;

        const float* c = cb + (size_t)n * DLAT;
        float dot = 0.f;
#pragma unroll
        for (int i = 0; i < 8; i++) dot += rv[i] * c[lane + 32 * i];
#pragma unroll
        for (int o = 16; o; o >>= 1) dot += __shfl_xor_sync(0xffffffffu, dot, o);

        float d = (rnorm - 2.0f * dot) + cbn[n];
        if (d < bestv || (d == bestv && n < bestn)) { bestv = d; bestn = n; }
    }
    const int bi = bestn;
    if (lane == 0) idx_out[row * 3 + stage] = bi;

    // straight-through update (replicates JAX numerics exactly)
    const float* c = cb + (size_t)bi * DLAT;
    float* q = zq + (size_t)row * DLAT;
    float se = 0.f;
#pragma unroll
    for (int i = 0; i < 8; i++) {
        int col = lane + 32 * i;
        float ev = c[col];
        float diff = rv[i] - ev;
        se += diff * diff;
        float t   = ev - rv[i];      // sg(e - r)
        float zqe = rv[i] + t;       // straight-through z_q
        r[col] = rv[i] - zqe;        // residual - sg(z_q)
        q[col] = (stage == 0) ? zqe : (q[col] + zqe);
    }
#pragma unroll
    for (int o = 16; o; o >>= 1) se += __shfl_xor_sync(0xffffffffu, se, o);
    if (lane == 0) {
        float m = se * (1.0f / 256.0f);
        float l = m + 0.25f * m;
        vloss[row] = (stage == 0) ? l : (vloss[row] + l);
    }
}

// ---------------------------------------------------------------------------
// Finalize: recon loss, total loss, idx -> float
// ---------------------------------------------------------------------------
__global__ __launch_bounds__(256)
void finalize_kernel(const float* __restrict__ x, const float* __restrict__ xhat,
                     const float* __restrict__ vloss, const int* __restrict__ idx,
                     float* __restrict__ out_loss, float* __restrict__ out_idx)
{
    int row  = blockIdx.x * 8 + (threadIdx.x >> 5);
    int lane = threadIdx.x & 31;

    const float* xr = x    + (size_t)row * D_IN;
    const float* hr = xhat + (size_t)row * D_IN;
    float s = 0.f;
#pragma unroll 8
    for (int i = 0; i < 64; i++) {
        int col = lane + 32 * i;
        float d = hr[col] - xr[col];
        s += d * d;
    }
#pragma unroll
    for (int o = 16; o; o >>= 1) s += __shfl_xor_sync(0xffffffffu, s, o);
    if (lane == 0) {
        float recon = s * (1.0f / 2048.0f);
        out_loss[row] = vloss[row] + recon;
    }
    if (lane < 3) out_idx[row * 3 + lane] = (float)idx[row * 3 + lane];
}

// ---------------------------------------------------------------------------
// Launch
// ---------------------------------------------------------------------------
extern "C" void kernel_launch(void* const* d_in, const int* in_sizes, int n_in,
                              void* d_out, int out_size)
{
    const float* x      = (const float*)d_in[0];
    const float* encW1  = (const float*)d_in[1];
    const float* encb1  = (const float*)d_in[2];
    const float* encW2  = (const float*)d_in[3];
    const float* encb2  = (const float*)d_in[4];
    const float* encW3  = (const float*)d_in[5];
    const float* encb3  = (const float*)d_in[6];
    const float* ln_g   = (const float*)d_in[7];
    const float* ln_b   = (const float*)d_in[8];
    const float* cb0    = (const float*)d_in[9];
    const float* cb1    = (const float*)d_in[10];
    const float* cb2    = (const float*)d_in[11];
    const float* decW1  = (const float*)d_in[12];
    const float* decb1  = (const float*)d_in[13];
    const float* decW2  = (const float*)d_in[14];
    const float* decb2  = (const float*)d_in[15];
    const float* decW3  = (const float*)d_in[16];
    const float* decb3  = (const float*)d_in[17];

    float *h1, *h2, *res, *zq, *vloss, *cbn;
    __half *w1h, *w1l, *w2h, *w2l, *w3h, *w3l;
    __half *d1h, *d1l, *d2h, *d2l, *d3h, *d3l, *cbh;
    int* idx;
    cudaGetSymbolAddress((void**)&h1, g_h1);
    cudaGetSymbolAddress((void**)&h2, g_h2);
    cudaGetSymbolAddress((void**)&res, g_res);
    cudaGetSymbolAddress((void**)&zq, g_zq);
    cudaGetSymbolAddress((void**)&vloss, g_vloss);
    cudaGetSymbolAddress((void**)&cbn, g_cbn);
    cudaGetSymbolAddress((void**)&idx, g_idx);
    cudaGetSymbolAddress((void**)&w1h, g_w1h); cudaGetSymbolAddress((void**)&w1l, g_w1l);
    cudaGetSymbolAddress((void**)&w2h, g_w2h); cudaGetSymbolAddress((void**)&w2l, g_w2l);
    cudaGetSymbolAddress((void**)&w3h, g_w3h); cudaGetSymbolAddress((void**)&w3l, g_w3l);
    cudaGetSymbolAddress((void**)&d1h, g_d1h); cudaGetSymbolAddress((void**)&d1l, g_d1l);
    cudaGetSymbolAddress((void**)&d2h, g_d2h); cudaGetSymbolAddress((void**)&d2l, g_d2l);
    cudaGetSymbolAddress((void**)&d3h, g_d3h); cudaGetSymbolAddress((void**)&d3l, g_d3l);
    cudaGetSymbolAddress((void**)&cbh, g_cbh);

    float* xhat     = (float*)d_out;
    float* out_loss = xhat + (size_t)BATCH * D_IN;
    float* out_idx  = out_loss + BATCH;

    const int SMEM3 = 2 * 16384;   // 32 KB
    const int SMEM1 = 2 * 8192;    // 16 KB
    cudaFuncSetAttribute((const void*)mma_gemm_h<3, true,  true >, cudaFuncAttributeMaxDynamicSharedMemorySize, SMEM3);
    cudaFuncSetAttribute((const void*)mma_gemm_h<3, false, true >, cudaFuncAttributeMaxDynamicSharedMemorySize, SMEM3);
    cudaFuncSetAttribute((const void*)mma_gemm_h<1, false, false>, cudaFuncAttributeMaxDynamicSharedMemorySize, SMEM1);
    cudaFuncSetAttribute((const void*)mma_gemm_h<1, true,  true >, cudaFuncAttributeMaxDynamicSharedMemorySize, SMEM1);
    cudaFuncSetAttribute((const void*)mma_gemm_h<1, false, true >, cudaFuncAttributeMaxDynamicSharedMemorySize, SMEM1);

    const dim3 blk(256);
    const dim3 tblk(32, 8);
    const int MB = BATCH / 128;          // 128
    const int warpGrid = BATCH / 8;      // 2048

    // ---- prep: transpose+split weights; codebook hi; codebook norms ----
    transpose_convert<<<dim3(H1D / 32, D_IN / 32), tblk>>>(encW1, w1h, w1l, D_IN, H1D);
    transpose_convert<<<dim3(H2D / 32, H1D / 32), tblk>>>(encW2, w2h, w2l, H1D, H2D);
    transpose_convert<<<dim3(DLAT / 32, H2D / 32), tblk>>>(encW3, w3h, w3l, H2D, DLAT);
    transpose_convert<<<dim3(H2D / 32, DLAT / 32), tblk>>>(decW1, d1h, d1l, DLAT, H2D);
    transpose_convert<<<dim3(H1D / 32, H2D / 32), tblk>>>(decW2, d2h, d2l, H2D, H1D);
    transpose_convert<<<dim3(D_IN / 32, H1D / 32), tblk>>>(decW3, d3h, d3l, H1D, D_IN);
    convert_cb_kernel<<<3 * KCODE * DLAT / 256, blk>>>(cb0, cb1, cb2, cbh);
    cbnorm_kernel<<<3 * KCODE / 8, blk>>>(cb0, cb1, cb2, cbn);

    // ---- encoder (fp16 split x3 ~ fp32 accuracy; feeds argmin) ----
    mma_gemm_h<3, true,  true ><<<dim3(H1D / 128, MB), blk, SMEM3>>>(x,  w1h, w1l, encb1, h1,  H1D,  D_IN);
    mma_gemm_h<3, true,  true ><<<dim3(H2D / 128, MB), blk, SMEM3>>>(h1, w2h, w2l, encb2, h2,  H2D,  H1D);
    mma_gemm_h<3, false, true ><<<dim3(DLAT / 128, MB), blk, SMEM3>>>(h2, w3h, w3l, encb3, res, DLAT, H2D);

    ln_kernel<<<warpGrid, blk>>>(res, ln_g, ln_b);

    // ---- residual VQ: approx scores (fp16 single) + exact refinement ----
    for (int s = 0; s < 3; s++) {
        const float* cb = (s == 0) ? cb0 : (s == 1 ? cb1 : cb2);
        mma_gemm_h<1, false, false><<<dim3(KCODE / 128, MB), blk, SMEM1>>>(res, cbh + (size_t)s * KCODE * DLAT, nullptr, nullptr, h1, KCODE, DLAT);
        vq_step<<<warpGrid, blk>>>(res, h1, cbn + s * KCODE, cb, zq, vloss, idx, s);
    }

    // ---- decoder (fp16 single-pass; post-argmin, tolerance-safe) ----
    mma_gemm_h<1, true,  true ><<<dim3(H2D / 128, MB), blk, SMEM1>>>(zq, d1h, nullptr, decb1, h2,   H2D,  DLAT);
    mma_gemm_h<1, true,  true ><<<dim3(H1D / 128, MB), blk, SMEM1>>>(h2, d2h, nullptr, decb2, h1,   H1D,  H2D);
    mma_gemm_h<1, false, true ><<<dim3(D_IN / 128, MB), blk, SMEM1>>>(h1, d3h, nullptr, decb3, xhat, D_IN, H1D);

    finalize_kernel<<<warpGrid, blk>>>(x, xhat, vloss, idx, out_loss, out_idx);
}